// round 3
// baseline (speedup 1.0000x reference)
#include <cuda_runtime.h>

#define Bz   4
#define Sz   4096
#define Hz   8
#define Lz   1024      // H * DI
#define N1z  384       // 3 * DO
#define NCH  128       // chunks over S
#define CLEN 32        // S / NCH
#define EPSf 1e-6f

typedef unsigned long long u64;

__device__ __forceinline__ void ffma2(u64& c, u64 a, u64 b) {
    asm("fma.rn.f32x2 %0, %1, %2, %0;" : "+l"(c) : "l"(a), "l"(b));
}

// ---------------- scratch (static device memory; no allocations) ----------------
static __device__ float  g_csum_ln[(size_t)Bz * Sz * Lz];        // 64 MB
static __device__ float  g_h3[(size_t)Bz * Sz * Hz * N1z];       // 192 MB
static __device__ float2 g_fgi[(size_t)Bz * Sz * Lz];            // 128 MB (f, i)
static __device__ float  g_cell[(size_t)Bz * Sz * Lz];           // 64 MB
static __device__ float  g_og[(size_t)Bz * Sz * Lz];             // 64 MB
static __device__ float  g_chA[Bz * NCH * Lz];
static __device__ float  g_chF[Bz * NCH * Lz];
static __device__ float  g_chAcc[Bz * NCH * Lz];
static __device__ float  g_carry[Bz * NCH * Lz];

// =====================================================================
// Phase 1: exclusive cumsum over S + LayerNorm over (H,DI) per (b,s)
// =====================================================================
__global__ void k_scan1_partial(const float* __restrict__ x) {
    const int b = blockIdx.x, ch = blockIdx.y, l = threadIdx.x;
    const float* p = x + (size_t)(b * Sz + ch * CLEN) * Lz + l;
    float s0 = 0.f, s1 = 0.f, s2 = 0.f, s3 = 0.f;
    #pragma unroll
    for (int i = 0; i < CLEN; i += 4) {
        s0 += p[(size_t)(i + 0) * Lz];
        s1 += p[(size_t)(i + 1) * Lz];
        s2 += p[(size_t)(i + 2) * Lz];
        s3 += p[(size_t)(i + 3) * Lz];
    }
    g_chA[(b * NCH + ch) * Lz + l] = (s0 + s1) + (s2 + s3);
}

__global__ void k_scan1_offsets() {
    const int b = blockIdx.x, l = threadIdx.x;
    float run = 0.f;
    #pragma unroll 4
    for (int ch = 0; ch < NCH; ch++) {
        const int idx = (b * NCH + ch) * Lz + l;
        const float t = g_chA[idx];
        g_chA[idx] = run;
        run += t;
    }
}

__global__ void k_scan1_ln(const float* __restrict__ x,
                           const float* __restrict__ gam,
                           const float* __restrict__ bet) {
    __shared__ float sred[64];
    __shared__ float s_stats[2];
    const int b = blockIdx.x, ch = blockIdx.y, l = threadIdx.x;
    const int wid = l >> 5, lane = l & 31;
    float c = g_chA[(b * NCH + ch) * Lz + l];
    const float gv = gam[l], bv = bet[l];
    const float* p = x + (size_t)(b * Sz + ch * CLEN) * Lz + l;
    float* o = g_csum_ln + (size_t)(b * Sz + ch * CLEN) * Lz + l;
    for (int i = 0; i < CLEN; i++) {
        const float v = c;
        float r1 = v, r2 = v * v;
        #pragma unroll
        for (int off = 16; off > 0; off >>= 1) {
            r1 += __shfl_down_sync(0xffffffffu, r1, off);
            r2 += __shfl_down_sync(0xffffffffu, r2, off);
        }
        if (lane == 0) { sred[wid] = r1; sred[32 + wid] = r2; }
        __syncthreads();
        if (wid == 0) {
            float t1 = sred[lane], t2 = sred[32 + lane];
            #pragma unroll
            for (int off = 16; off > 0; off >>= 1) {
                t1 += __shfl_down_sync(0xffffffffu, t1, off);
                t2 += __shfl_down_sync(0xffffffffu, t2, off);
            }
            if (lane == 0) {
                const float mu = t1 * (1.f / 1024.f);
                s_stats[0] = mu;
                s_stats[1] = rsqrtf(t2 * (1.f / 1024.f) - mu * mu + EPSf);
            }
        }
        __syncthreads();
        o[(size_t)i * Lz] = (v - s_stats[0]) * s_stats[1] * gv + bv;
        c += p[(size_t)i * Lz];
    }
}

// =====================================================================
// Batched per-head SGEMM via packed fma.rn.f32x2 (dual fp32 pipe).
// 128x128 tile, BK=8, 256 threads, 8x8 per thread, B duplicated in smem.
// =====================================================================
template <int NLD, bool PHASE1>
__global__ __launch_bounds__(256, 2) void k_gemm(const float* __restrict__ A0,
                                                 const float* __restrict__ W,
                                                 const float* __restrict__ bias) {
    const float* __restrict__ A1 = PHASE1 ? g_csum_ln : g_cell;
    float* __restrict__ C = PHASE1 ? g_h3 : g_og;

    const int mt = blockIdx.x, nt = blockIdx.y, h = blockIdx.z;
    const int tid = threadIdx.x;
    const int m0 = mt * 128, n0 = nt * 128;

    __shared__ float As[2][8][128];
    __shared__ float Bs[2][8][256];   // duplicated pairs: Bs[k][2n]=Bs[k][2n+1]=b_n

    const int am = tid >> 1;            // 0..127 (row in A tile)
    const int ak = (tid & 1) * 4;       // 0 or 4
    const int bk = tid >> 5;            // 0..7
    const int bn = (tid & 31) * 4;      // 0..124

    const float* Wh = W + (size_t)h * 256 * NLD;
    const size_t arow = ((size_t)(m0 + am) * Hz + h) * 128;

    const int tr = (tid >> 4) * 8;      // output row base (8 rows)
    const int tc = (tid & 15) * 8;      // output col base (8 cols)

    u64 acc[4][8];                      // acc[ip][j]: rows (tr+2ip, tr+2ip+1), col tc+j
    #pragma unroll
    for (int ip = 0; ip < 4; ip++)
        #pragma unroll
        for (int j = 0; j < 8; j++) acc[ip][j] = 0ull;

    // prefetch k-tile 0 (always from A0)
    {
        float4 a4 = *(const float4*)(A0 + arow + ak);
        float4 b4 = *(const float4*)(Wh + (size_t)bk * NLD + n0 + bn);
        As[0][ak + 0][am] = a4.x;
        As[0][ak + 1][am] = a4.y;
        As[0][ak + 2][am] = a4.z;
        As[0][ak + 3][am] = a4.w;
        *(float4*)(&Bs[0][bk][2 * bn])     = make_float4(b4.x, b4.x, b4.y, b4.y);
        *(float4*)(&Bs[0][bk][2 * bn + 4]) = make_float4(b4.z, b4.z, b4.w, b4.w);
    }
    __syncthreads();

    #pragma unroll 1
    for (int kt = 0; kt < 32; kt++) {
        const int cur = kt & 1;
        float4 na4, nb4;
        if (kt < 31) {
            const int k2 = kt + 1;
            const float* Asrc = (k2 < 16) ? A0 : A1;
            const int koff = (k2 & 15) * 8;
            na4 = *(const float4*)(Asrc + arow + koff + ak);
            nb4 = *(const float4*)(Wh + (size_t)(k2 * 8 + bk) * NLD + n0 + bn);
        }
        #pragma unroll
        for (int kk = 0; kk < 8; kk++) {
            u64 ap[4];
            *(float4*)(ap)     = *(const float4*)(&As[cur][kk][tr]);
            *(float4*)(ap + 2) = *(const float4*)(&As[cur][kk][tr + 4]);
            u64 bp[4];
            *(float4*)(bp)     = *(const float4*)(&Bs[cur][kk][2 * tc]);
            *(float4*)(bp + 2) = *(const float4*)(&Bs[cur][kk][2 * tc + 4]);
            #pragma unroll
            for (int ip = 0; ip < 4; ip++)
                #pragma unroll
                for (int j = 0; j < 4; j++)
                    ffma2(acc[ip][j], ap[ip], bp[j]);
            *(float4*)(bp)     = *(const float4*)(&Bs[cur][kk][2 * tc + 8]);
            *(float4*)(bp + 2) = *(const float4*)(&Bs[cur][kk][2 * tc + 12]);
            #pragma unroll
            for (int ip = 0; ip < 4; ip++)
                #pragma unroll
                for (int j = 0; j < 4; j++)
                    ffma2(acc[ip][j + 4], ap[ip], bp[j]);
        }
        if (kt < 31) {
            const int nxt = cur ^ 1;
            As[nxt][ak + 0][am] = na4.x;
            As[nxt][ak + 1][am] = na4.y;
            As[nxt][ak + 2][am] = na4.z;
            As[nxt][ak + 3][am] = na4.w;
            *(float4*)(&Bs[nxt][bk][2 * bn])     = make_float4(nb4.x, nb4.x, nb4.y, nb4.y);
            *(float4*)(&Bs[nxt][bk][2 * bn + 4]) = make_float4(nb4.z, nb4.z, nb4.w, nb4.w);
            __syncthreads();
        }
    }

    float bv[8];
    *(float4*)(bv)     = *(const float4*)(bias + h * NLD + n0 + tc);
    *(float4*)(bv + 4) = *(const float4*)(bias + h * NLD + n0 + tc + 4);
    #pragma unroll
    for (int i = 0; i < 8; i++) {
        const int ip = i >> 1, hi = i & 1;
        const size_t crow = ((size_t)(m0 + tr + i) * Hz + h) * NLD + n0 + tc;
        float o[8];
        #pragma unroll
        for (int j = 0; j < 8; j++) {
            float2 p = *(float2*)(&acc[ip][j]);
            o[j] = (hi ? p.y : p.x) + bv[j];
        }
        *(float4*)(C + crow)     = *(float4*)(o);
        *(float4*)(C + crow + 4) = *(float4*)(o + 4);
    }
}

// =====================================================================
// Phase 3: LN over (H,3,DO) per (b,s), gates, per-chunk scan composition
// =====================================================================
__global__ void k_gates(const float* __restrict__ gam, const float* __restrict__ bet) {
    __shared__ float row[3072];
    __shared__ float sred[64];
    __shared__ float s_stats[2];
    const int b = blockIdx.x, ch = blockIdx.y, l = threadIdx.x;
    const int wid = l >> 5, lane = l & 31;
    const int h = l >> 7, dd = l & 127;
    const int pb = (h * 3) * 128 + dd;
    const float gi = gam[pb], gf = gam[pb + 128], gh = gam[pb + 256];
    const float bi = bet[pb], bf = bet[pb + 128], bh = bet[pb + 256];
    float F = 1.f, Acc = 0.f;
    for (int i = 0; i < CLEN; i++) {
        const size_t rb = (size_t)(b * Sz + ch * CLEN + i) * (Hz * N1z);
        const float v0 = g_h3[rb + l];
        const float v1 = g_h3[rb + 1024 + l];
        const float v2 = g_h3[rb + 2048 + l];
        row[l] = v0; row[1024 + l] = v1; row[2048 + l] = v2;
        float r1 = v0 + v1 + v2;
        float r2 = v0 * v0 + v1 * v1 + v2 * v2;
        #pragma unroll
        for (int off = 16; off > 0; off >>= 1) {
            r1 += __shfl_down_sync(0xffffffffu, r1, off);
            r2 += __shfl_down_sync(0xffffffffu, r2, off);
        }
        if (lane == 0) { sred[wid] = r1; sred[32 + wid] = r2; }
        __syncthreads();
        if (wid == 0) {
            float t1 = sred[lane], t2 = sred[32 + lane];
            #pragma unroll
            for (int off = 16; off > 0; off >>= 1) {
                t1 += __shfl_down_sync(0xffffffffu, t1, off);
                t2 += __shfl_down_sync(0xffffffffu, t2, off);
            }
            if (lane == 0) {
                const float mu = t1 * (1.f / 3072.f);
                s_stats[0] = mu;
                s_stats[1] = rsqrtf(t2 * (1.f / 3072.f) - mu * mu + EPSf);
            }
        }
        __syncthreads();
        const float mu = s_stats[0], rs = s_stats[1];
        const int base = h * N1z + dd;
        const float xig = (row[base]       - mu) * rs * gi + bi;
        const float xfg = (row[base + 128] - mu) * rs * gf + bf;
        const float xhd = (row[base + 256] - mu) * rs * gh + bh;
        const float f  = 1.f / (1.f + __expf(-xfg));
        const float ii = (1.f / (1.f + __expf(-xig))) * fmaxf(xhd, 0.f);
        g_fgi[(size_t)(b * Sz + ch * CLEN + i) * Lz + l] = make_float2(f, ii);
        Acc = f * Acc + ii;
        F *= f;
        __syncthreads();
    }
    const int ci = (b * NCH + ch) * Lz + l;
    g_chF[ci] = F;
    g_chAcc[ci] = Acc;
}

__global__ void k_carry(const float* __restrict__ init_cx) {
    const int b = blockIdx.x, l = threadIdx.x;
    float c = init_cx[l];
    #pragma unroll 4
    for (int ch = 0; ch < NCH; ch++) {
        const int idx = (b * NCH + ch) * Lz + l;
        g_carry[idx] = c;
        c = g_chF[idx] * c + g_chAcc[idx];
    }
}

__global__ void k_replay() {
    const int b = blockIdx.x, ch = blockIdx.y, l = threadIdx.x;
    float c = g_carry[(b * NCH + ch) * Lz + l];
    const size_t base = (size_t)(b * Sz + ch * CLEN) * Lz + l;
    #pragma unroll 4
    for (int i = 0; i < CLEN; i++) {
        const float2 fi = g_fgi[base + (size_t)i * Lz];
        c = fi.x * c + fi.y;
        g_cell[base + (size_t)i * Lz] = c;
    }
}

// =====================================================================
// Phase 5: LN over (H,DO) per (b,s), sigmoid(og) * cell -> out
// =====================================================================
__global__ void k_final(const float* __restrict__ gam, const float* __restrict__ bet,
                        float* __restrict__ out) {
    __shared__ float sred[16];
    __shared__ float s_stats[2];
    const int bs = blockIdx.x, t = threadIdx.x;
    const int wid = t >> 5, lane = t & 31;
    const size_t base = (size_t)bs * Lz + t * 4;
    const float4 v = *(const float4*)(g_og + base);
    float r1 = v.x + v.y + v.z + v.w;
    float r2 = v.x * v.x + v.y * v.y + v.z * v.z + v.w * v.w;
    #pragma unroll
    for (int off = 16; off > 0; off >>= 1) {
        r1 += __shfl_down_sync(0xffffffffu, r1, off);
        r2 += __shfl_down_sync(0xffffffffu, r2, off);
    }
    if (lane == 0) { sred[wid] = r1; sred[8 + wid] = r2; }
    __syncthreads();
    if (wid == 0) {
        float t1 = lane < 8 ? sred[lane] : 0.f;
        float t2 = lane < 8 ? sred[8 + lane] : 0.f;
        #pragma unroll
        for (int off = 4; off > 0; off >>= 1) {
            t1 += __shfl_down_sync(0xffffffffu, t1, off);
            t2 += __shfl_down_sync(0xffffffffu, t2, off);
        }
        if (lane == 0) {
            const float mu = t1 * (1.f / 1024.f);
            s_stats[0] = mu;
            s_stats[1] = rsqrtf(t2 * (1.f / 1024.f) - mu * mu + EPSf);
        }
    }
    __syncthreads();
    const float mu = s_stats[0], rs = s_stats[1];
    const float4 cc = *(const float4*)(g_cell + base);
    const float4 gg = *(const float4*)(gam + t * 4);
    const float4 bb = *(const float4*)(bet + t * 4);
    float4 o;
    o.x = cc.x / (1.f + __expf(-((v.x - mu) * rs * gg.x + bb.x)));
    o.y = cc.y / (1.f + __expf(-((v.y - mu) * rs * gg.y + bb.y)));
    o.z = cc.z / (1.f + __expf(-((v.z - mu) * rs * gg.z + bb.z)));
    o.w = cc.w / (1.f + __expf(-((v.w - mu) * rs * gg.w + bb.w)));
    *(float4*)(out + base) = o;
}

// =====================================================================
extern "C" void kernel_launch(void* const* d_in, const int* in_sizes, int n_in,
                              void* d_out, int out_size) {
    (void)in_sizes; (void)n_in; (void)out_size;
    const float* x       = (const float*)d_in[0];
    const float* W_hid   = (const float*)d_in[1];
    const float* b_hid   = (const float*)d_in[2];
    const float* g_cs    = (const float*)d_in[3];
    const float* be_cs   = (const float*)d_in[4];
    const float* g_hd    = (const float*)d_in[5];
    const float* be_hd   = (const float*)d_in[6];
    const float* W_og    = (const float*)d_in[7];
    const float* b_og    = (const float*)d_in[8];
    const float* g_ogp   = (const float*)d_in[9];
    const float* be_ogp  = (const float*)d_in[10];
    const float* init_cx = (const float*)d_in[11];
    float* out = (float*)d_out;

    // Phase 1: exclusive cumsum + LN(csum)
    k_scan1_partial<<<dim3(Bz, NCH), 1024>>>(x);
    k_scan1_offsets<<<Bz, 1024>>>();
    k_scan1_ln<<<dim3(Bz, NCH), 1024>>>(x, g_cs, be_cs);

    // Phase 2: h3 = [x | ln(csum)] @ W_hid + b_hid
    k_gemm<N1z, true><<<dim3(Sz * Bz / 128, N1z / 128, Hz), 256>>>(x, W_hid, b_hid);

    // Phase 3: LN(h3), gates, chunk compositions
    k_gates<<<dim3(Bz, NCH), 1024>>>(g_hd, be_hd);

    // Phase 4: recurrent scan c = f*c + i
    k_carry<<<Bz, 1024>>>(init_cx);
    k_replay<<<dim3(Bz, NCH), 1024>>>();

    // Phase 5: og = [x | cell] @ W_og + b_og, LN, sigmoid*cell
    k_gemm<128, false><<<dim3(Sz * Bz / 128, 1, Hz), 256>>>(x, W_og, b_og);
    k_final<<<Bz * Sz, 256>>>(g_ogp, be_ogp, out);
}

// round 4
// speedup vs baseline: 1.0007x; 1.0007x over previous
#include <cuda_runtime.h>

#define Bz   4
#define Sz   4096
#define Hz   8
#define Lz   1024      // H * DI
#define N1z  384       // 3 * DO
#define NCH  128       // chunks over S
#define CLEN 32        // S / NCH
#define EPSf 1e-6f

typedef unsigned long long u64;

__device__ __forceinline__ void ffma2(u64& c, u64 a, u64 b) {
    asm("fma.rn.f32x2 %0, %1, %2, %0;" : "+l"(c) : "l"(a), "l"(b));
}

// ---------------- scratch (static device memory; no allocations) ----------------
static __device__ float  g_csum_ln[(size_t)Bz * Sz * Lz];        // 64 MB
static __device__ float  g_h3[(size_t)Bz * Sz * Hz * N1z];       // 192 MB
static __device__ float2 g_fgi[(size_t)Bz * Sz * Lz];            // 128 MB (f, i)
static __device__ float  g_cell[(size_t)Bz * Sz * Lz];           // 64 MB
static __device__ float  g_og[(size_t)Bz * Sz * Lz];             // 64 MB
static __device__ float  g_chA[Bz * NCH * Lz];
static __device__ float  g_chF[Bz * NCH * Lz];
static __device__ float  g_chAcc[Bz * NCH * Lz];
static __device__ float  g_carry[Bz * NCH * Lz];

// =====================================================================
// Phase 1: exclusive cumsum over S + LayerNorm over (H,DI) per (b,s)
// =====================================================================
__global__ void k_scan1_partial(const float* __restrict__ x) {
    const int b = blockIdx.x, ch = blockIdx.y, l = threadIdx.x;
    const float* p = x + (size_t)(b * Sz + ch * CLEN) * Lz + l;
    float s0 = 0.f, s1 = 0.f, s2 = 0.f, s3 = 0.f;
    #pragma unroll
    for (int i = 0; i < CLEN; i += 4) {
        s0 += p[(size_t)(i + 0) * Lz];
        s1 += p[(size_t)(i + 1) * Lz];
        s2 += p[(size_t)(i + 2) * Lz];
        s3 += p[(size_t)(i + 3) * Lz];
    }
    g_chA[(b * NCH + ch) * Lz + l] = (s0 + s1) + (s2 + s3);
}

__global__ void k_scan1_offsets() {
    const int b = blockIdx.x, l = threadIdx.x;
    float run = 0.f;
    #pragma unroll 4
    for (int ch = 0; ch < NCH; ch++) {
        const int idx = (b * NCH + ch) * Lz + l;
        const float t = g_chA[idx];
        g_chA[idx] = run;
        run += t;
    }
}

__global__ void k_scan1_ln(const float* __restrict__ x,
                           const float* __restrict__ gam,
                           const float* __restrict__ bet) {
    __shared__ float sred[64];
    __shared__ float s_stats[2];
    const int b = blockIdx.x, ch = blockIdx.y, l = threadIdx.x;
    const int wid = l >> 5, lane = l & 31;
    float c = g_chA[(b * NCH + ch) * Lz + l];
    const float gv = gam[l], bv = bet[l];
    const float* p = x + (size_t)(b * Sz + ch * CLEN) * Lz + l;
    float* o = g_csum_ln + (size_t)(b * Sz + ch * CLEN) * Lz + l;
    for (int i = 0; i < CLEN; i++) {
        const float v = c;
        float r1 = v, r2 = v * v;
        #pragma unroll
        for (int off = 16; off > 0; off >>= 1) {
            r1 += __shfl_down_sync(0xffffffffu, r1, off);
            r2 += __shfl_down_sync(0xffffffffu, r2, off);
        }
        if (lane == 0) { sred[wid] = r1; sred[32 + wid] = r2; }
        __syncthreads();
        if (wid == 0) {
            float t1 = sred[lane], t2 = sred[32 + lane];
            #pragma unroll
            for (int off = 16; off > 0; off >>= 1) {
                t1 += __shfl_down_sync(0xffffffffu, t1, off);
                t2 += __shfl_down_sync(0xffffffffu, t2, off);
            }
            if (lane == 0) {
                const float mu = t1 * (1.f / 1024.f);
                s_stats[0] = mu;
                s_stats[1] = rsqrtf(t2 * (1.f / 1024.f) - mu * mu + EPSf);
            }
        }
        __syncthreads();
        o[(size_t)i * Lz] = (v - s_stats[0]) * s_stats[1] * gv + bv;
        c += p[(size_t)i * Lz];
    }
}

// =====================================================================
// Batched per-head SGEMM via packed fma.rn.f32x2 (dual fp32 pipe).
// 128x128 tile, BK=8, 256 threads, 8x8 per thread, B duplicated in smem.
// =====================================================================
template <int NLD, bool PHASE1>
__global__ __launch_bounds__(256, 2) void k_gemm(const float* __restrict__ A0,
                                                 const float* __restrict__ W,
                                                 const float* __restrict__ bias) {
    const float* __restrict__ A1 = PHASE1 ? g_csum_ln : g_cell;
    float* __restrict__ C = PHASE1 ? g_h3 : g_og;

    const int mt = blockIdx.x, nt = blockIdx.y, h = blockIdx.z;
    const int tid = threadIdx.x;
    const int m0 = mt * 128, n0 = nt * 128;

    __shared__ float As[2][8][128];
    __shared__ float Bs[2][8][256];   // duplicated pairs: Bs[k][2n]=Bs[k][2n+1]=b_n

    const int am = tid >> 1;            // 0..127 (row in A tile)
    const int ak = (tid & 1) * 4;       // 0 or 4
    const int bk = tid >> 5;            // 0..7
    const int bn = (tid & 31) * 4;      // 0..124

    const float* Wh = W + (size_t)h * 256 * NLD;
    const size_t arow = ((size_t)(m0 + am) * Hz + h) * 128;

    const int tr = (tid >> 4) * 8;      // output row base (8 rows)
    const int tc = (tid & 15) * 8;      // output col base (8 cols)

    u64 acc[4][8];                      // acc[ip][j]: rows (tr+2ip, tr+2ip+1), col tc+j
    #pragma unroll
    for (int ip = 0; ip < 4; ip++)
        #pragma unroll
        for (int j = 0; j < 8; j++) acc[ip][j] = 0ull;

    // prefetch k-tile 0 (always from A0)
    {
        float4 a4 = *(const float4*)(A0 + arow + ak);
        float4 b4 = *(const float4*)(Wh + (size_t)bk * NLD + n0 + bn);
        As[0][ak + 0][am] = a4.x;
        As[0][ak + 1][am] = a4.y;
        As[0][ak + 2][am] = a4.z;
        As[0][ak + 3][am] = a4.w;
        *(float4*)(&Bs[0][bk][2 * bn])     = make_float4(b4.x, b4.x, b4.y, b4.y);
        *(float4*)(&Bs[0][bk][2 * bn + 4]) = make_float4(b4.z, b4.z, b4.w, b4.w);
    }
    __syncthreads();

    #pragma unroll 1
    for (int kt = 0; kt < 32; kt++) {
        const int cur = kt & 1;
        float4 na4, nb4;
        if (kt < 31) {
            const int k2 = kt + 1;
            const float* Asrc = (k2 < 16) ? A0 : A1;
            const int koff = (k2 & 15) * 8;
            na4 = *(const float4*)(Asrc + arow + koff + ak);
            nb4 = *(const float4*)(Wh + (size_t)(k2 * 8 + bk) * NLD + n0 + bn);
        }
        #pragma unroll
        for (int kk = 0; kk < 8; kk++) {
            u64 ap[4];
            *(float4*)(ap)     = *(const float4*)(&As[cur][kk][tr]);
            *(float4*)(ap + 2) = *(const float4*)(&As[cur][kk][tr + 4]);
            u64 bp[4];
            *(float4*)(bp)     = *(const float4*)(&Bs[cur][kk][2 * tc]);
            *(float4*)(bp + 2) = *(const float4*)(&Bs[cur][kk][2 * tc + 4]);
            #pragma unroll
            for (int ip = 0; ip < 4; ip++)
                #pragma unroll
                for (int j = 0; j < 4; j++)
                    ffma2(acc[ip][j], ap[ip], bp[j]);
            *(float4*)(bp)     = *(const float4*)(&Bs[cur][kk][2 * tc + 8]);
            *(float4*)(bp + 2) = *(const float4*)(&Bs[cur][kk][2 * tc + 12]);
            #pragma unroll
            for (int ip = 0; ip < 4; ip++)
                #pragma unroll
                for (int j = 0; j < 4; j++)
                    ffma2(acc[ip][j + 4], ap[ip], bp[j]);
        }
        if (kt < 31) {
            const int nxt = cur ^ 1;
            As[nxt][ak + 0][am] = na4.x;
            As[nxt][ak + 1][am] = na4.y;
            As[nxt][ak + 2][am] = na4.z;
            As[nxt][ak + 3][am] = na4.w;
            *(float4*)(&Bs[nxt][bk][2 * bn])     = make_float4(nb4.x, nb4.x, nb4.y, nb4.y);
            *(float4*)(&Bs[nxt][bk][2 * bn + 4]) = make_float4(nb4.z, nb4.z, nb4.w, nb4.w);
            __syncthreads();
        }
    }

    float bv[8];
    *(float4*)(bv)     = *(const float4*)(bias + h * NLD + n0 + tc);
    *(float4*)(bv + 4) = *(const float4*)(bias + h * NLD + n0 + tc + 4);
    #pragma unroll
    for (int i = 0; i < 8; i++) {
        const int ip = i >> 1, hi = i & 1;
        const size_t crow = ((size_t)(m0 + tr + i) * Hz + h) * NLD + n0 + tc;
        float o[8];
        #pragma unroll
        for (int j = 0; j < 8; j++) {
            float2 p = *(float2*)(&acc[ip][j]);
            o[j] = (hi ? p.y : p.x) + bv[j];
        }
        *(float4*)(C + crow)     = *(float4*)(o);
        *(float4*)(C + crow + 4) = *(float4*)(o + 4);
    }
}

// =====================================================================
// Phase 3: LN over (H,3,DO) per (b,s), gates, per-chunk scan composition
// =====================================================================
__global__ void k_gates(const float* __restrict__ gam, const float* __restrict__ bet) {
    __shared__ float row[3072];
    __shared__ float sred[64];
    __shared__ float s_stats[2];
    const int b = blockIdx.x, ch = blockIdx.y, l = threadIdx.x;
    const int wid = l >> 5, lane = l & 31;
    const int h = l >> 7, dd = l & 127;
    const int pb = (h * 3) * 128 + dd;
    const float gi = gam[pb], gf = gam[pb + 128], gh = gam[pb + 256];
    const float bi = bet[pb], bf = bet[pb + 128], bh = bet[pb + 256];
    float F = 1.f, Acc = 0.f;
    for (int i = 0; i < CLEN; i++) {
        const size_t rb = (size_t)(b * Sz + ch * CLEN + i) * (Hz * N1z);
        const float v0 = g_h3[rb + l];
        const float v1 = g_h3[rb + 1024 + l];
        const float v2 = g_h3[rb + 2048 + l];
        row[l] = v0; row[1024 + l] = v1; row[2048 + l] = v2;
        float r1 = v0 + v1 + v2;
        float r2 = v0 * v0 + v1 * v1 + v2 * v2;
        #pragma unroll
        for (int off = 16; off > 0; off >>= 1) {
            r1 += __shfl_down_sync(0xffffffffu, r1, off);
            r2 += __shfl_down_sync(0xffffffffu, r2, off);
        }
        if (lane == 0) { sred[wid] = r1; sred[32 + wid] = r2; }
        __syncthreads();
        if (wid == 0) {
            float t1 = sred[lane], t2 = sred[32 + lane];
            #pragma unroll
            for (int off = 16; off > 0; off >>= 1) {
                t1 += __shfl_down_sync(0xffffffffu, t1, off);
                t2 += __shfl_down_sync(0xffffffffu, t2, off);
            }
            if (lane == 0) {
                const float mu = t1 * (1.f / 3072.f);
                s_stats[0] = mu;
                s_stats[1] = rsqrtf(t2 * (1.f / 3072.f) - mu * mu + EPSf);
            }
        }
        __syncthreads();
        const float mu = s_stats[0], rs = s_stats[1];
        const int base = h * N1z + dd;
        const float xig = (row[base]       - mu) * rs * gi + bi;
        const float xfg = (row[base + 128] - mu) * rs * gf + bf;
        const float xhd = (row[base + 256] - mu) * rs * gh + bh;
        const float f  = 1.f / (1.f + __expf(-xfg));
        const float ii = (1.f / (1.f + __expf(-xig))) * fmaxf(xhd, 0.f);
        g_fgi[(size_t)(b * Sz + ch * CLEN + i) * Lz + l] = make_float2(f, ii);
        Acc = f * Acc + ii;
        F *= f;
        __syncthreads();
    }
    const int ci = (b * NCH + ch) * Lz + l;
    g_chF[ci] = F;
    g_chAcc[ci] = Acc;
}

__global__ void k_carry(const float* __restrict__ init_cx) {
    const int b = blockIdx.x, l = threadIdx.x;
    float c = init_cx[l];
    #pragma unroll 4
    for (int ch = 0; ch < NCH; ch++) {
        const int idx = (b * NCH + ch) * Lz + l;
        g_carry[idx] = c;
        c = g_chF[idx] * c + g_chAcc[idx];
    }
}

__global__ void k_replay() {
    const int b = blockIdx.x, ch = blockIdx.y, l = threadIdx.x;
    float c = g_carry[(b * NCH + ch) * Lz + l];
    const size_t base = (size_t)(b * Sz + ch * CLEN) * Lz + l;
    #pragma unroll 4
    for (int i = 0; i < CLEN; i++) {
        const float2 fi = g_fgi[base + (size_t)i * Lz];
        c = fi.x * c + fi.y;
        g_cell[base + (size_t)i * Lz] = c;
    }
}

// =====================================================================
// Phase 5: LN over (H,DO) per (b,s), sigmoid(og) * cell -> out
// =====================================================================
__global__ void k_final(const float* __restrict__ gam, const float* __restrict__ bet,
                        float* __restrict__ out) {
    __shared__ float sred[16];
    __shared__ float s_stats[2];
    const int bs = blockIdx.x, t = threadIdx.x;
    const int wid = t >> 5, lane = t & 31;
    const size_t base = (size_t)bs * Lz + t * 4;
    const float4 v = *(const float4*)(g_og + base);
    float r1 = v.x + v.y + v.z + v.w;
    float r2 = v.x * v.x + v.y * v.y + v.z * v.z + v.w * v.w;
    #pragma unroll
    for (int off = 16; off > 0; off >>= 1) {
        r1 += __shfl_down_sync(0xffffffffu, r1, off);
        r2 += __shfl_down_sync(0xffffffffu, r2, off);
    }
    if (lane == 0) { sred[wid] = r1; sred[8 + wid] = r2; }
    __syncthreads();
    if (wid == 0) {
        float t1 = lane < 8 ? sred[lane] : 0.f;
        float t2 = lane < 8 ? sred[8 + lane] : 0.f;
        #pragma unroll
        for (int off = 4; off > 0; off >>= 1) {
            t1 += __shfl_down_sync(0xffffffffu, t1, off);
            t2 += __shfl_down_sync(0xffffffffu, t2, off);
        }
        if (lane == 0) {
            const float mu = t1 * (1.f / 1024.f);
            s_stats[0] = mu;
            s_stats[1] = rsqrtf(t2 * (1.f / 1024.f) - mu * mu + EPSf);
        }
    }
    __syncthreads();
    const float mu = s_stats[0], rs = s_stats[1];
    const float4 cc = *(const float4*)(g_cell + base);
    const float4 gg = *(const float4*)(gam + t * 4);
    const float4 bb = *(const float4*)(bet + t * 4);
    float4 o;
    o.x = cc.x / (1.f + __expf(-((v.x - mu) * rs * gg.x + bb.x)));
    o.y = cc.y / (1.f + __expf(-((v.y - mu) * rs * gg.y + bb.y)));
    o.z = cc.z / (1.f + __expf(-((v.z - mu) * rs * gg.z + bb.z)));
    o.w = cc.w / (1.f + __expf(-((v.w - mu) * rs * gg.w + bb.w)));
    *(float4*)(out + base) = o;
}

// =====================================================================
extern "C" void kernel_launch(void* const* d_in, const int* in_sizes, int n_in,
                              void* d_out, int out_size) {
    (void)in_sizes; (void)n_in; (void)out_size;
    const float* x       = (const float*)d_in[0];
    const float* W_hid   = (const float*)d_in[1];
    const float* b_hid   = (const float*)d_in[2];
    const float* g_cs    = (const float*)d_in[3];
    const float* be_cs   = (const float*)d_in[4];
    const float* g_hd    = (const float*)d_in[5];
    const float* be_hd   = (const float*)d_in[6];
    const float* W_og    = (const float*)d_in[7];
    const float* b_og    = (const float*)d_in[8];
    const float* g_ogp   = (const float*)d_in[9];
    const float* be_ogp  = (const float*)d_in[10];
    const float* init_cx = (const float*)d_in[11];
    float* out = (float*)d_out;

    // Phase 1: exclusive cumsum + LN(csum)
    k_scan1_partial<<<dim3(Bz, NCH), 1024>>>(x);
    k_scan1_offsets<<<Bz, 1024>>>();
    k_scan1_ln<<<dim3(Bz, NCH), 1024>>>(x, g_cs, be_cs);

    // Phase 2: h3 = [x | ln(csum)] @ W_hid + b_hid
    k_gemm<N1z, true><<<dim3(Sz * Bz / 128, N1z / 128, Hz), 256>>>(x, W_hid, b_hid);

    // Phase 3: LN(h3), gates, chunk compositions
    k_gates<<<dim3(Bz, NCH), 1024>>>(g_hd, be_hd);

    // Phase 4: recurrent scan c = f*c + i
    k_carry<<<Bz, 1024>>>(init_cx);
    k_replay<<<dim3(Bz, NCH), 1024>>>();

    // Phase 5: og = [x | cell] @ W_og + b_og, LN, sigmoid*cell
    k_gemm<128, false><<<dim3(Sz * Bz / 128, 1, Hz), 256>>>(x, W_og, b_og);
    k_final<<<Bz * Sz, 256>>>(g_ogp, be_ogp, out);
}

// round 5
// speedup vs baseline: 2.1187x; 2.1173x over previous
#include <cuda_runtime.h>

#define Bz   4
#define Sz   4096
#define Hz   8
#define Lz   1024      // H * DI
#define N1z  384       // 3 * DO
#define NCH  128       // chunks over S
#define CLEN 32        // S / NCH
#define EPSf 1e-6f

// ---------------- scratch (static device memory; no allocations) ----------------
static __device__ float  g_csum_ln[(size_t)Bz * Sz * Lz];        // 64 MB
static __device__ float  g_h3[(size_t)Bz * Sz * Hz * N1z];       // 192 MB
static __device__ float2 g_fgi[(size_t)Bz * Sz * Lz];            // 128 MB (f, i)
static __device__ float  g_cell[(size_t)Bz * Sz * Lz];           // 64 MB
static __device__ float  g_og[(size_t)Bz * Sz * Lz];             // 64 MB
static __device__ float  g_chA[Bz * NCH * Lz];
static __device__ float  g_chF[Bz * NCH * Lz];
static __device__ float  g_chAcc[Bz * NCH * Lz];
static __device__ float  g_carry[Bz * NCH * Lz];

// =====================================================================
// Phase 1: exclusive cumsum over S + LayerNorm over (H,DI) per (b,s)
// =====================================================================
__global__ void k_scan1_partial(const float* __restrict__ x) {
    const int b = blockIdx.x, ch = blockIdx.y, l = threadIdx.x;
    const float* p = x + (size_t)(b * Sz + ch * CLEN) * Lz + l;
    float s0 = 0.f, s1 = 0.f, s2 = 0.f, s3 = 0.f;
    #pragma unroll
    for (int i = 0; i < CLEN; i += 4) {
        s0 += p[(size_t)(i + 0) * Lz];
        s1 += p[(size_t)(i + 1) * Lz];
        s2 += p[(size_t)(i + 2) * Lz];
        s3 += p[(size_t)(i + 3) * Lz];
    }
    g_chA[(b * NCH + ch) * Lz + l] = (s0 + s1) + (s2 + s3);
}

__global__ void k_scan1_offsets() {
    const int b = blockIdx.x, l = threadIdx.x;
    float run = 0.f;
    #pragma unroll 4
    for (int ch = 0; ch < NCH; ch++) {
        const int idx = (b * NCH + ch) * Lz + l;
        const float t = g_chA[idx];
        g_chA[idx] = run;
        run += t;
    }
}

__global__ void k_scan1_ln(const float* __restrict__ x,
                           const float* __restrict__ gam,
                           const float* __restrict__ bet) {
    __shared__ float sred[64];
    __shared__ float s_stats[2];
    const int b = blockIdx.x, ch = blockIdx.y, l = threadIdx.x;
    const int wid = l >> 5, lane = l & 31;
    float c = g_chA[(b * NCH + ch) * Lz + l];
    const float gv = gam[l], bv = bet[l];
    const float* p = x + (size_t)(b * Sz + ch * CLEN) * Lz + l;
    float* o = g_csum_ln + (size_t)(b * Sz + ch * CLEN) * Lz + l;
    for (int i = 0; i < CLEN; i++) {
        const float v = c;
        float r1 = v, r2 = v * v;
        #pragma unroll
        for (int off = 16; off > 0; off >>= 1) {
            r1 += __shfl_down_sync(0xffffffffu, r1, off);
            r2 += __shfl_down_sync(0xffffffffu, r2, off);
        }
        if (lane == 0) { sred[wid] = r1; sred[32 + wid] = r2; }
        __syncthreads();
        if (wid == 0) {
            float t1 = sred[lane], t2 = sred[32 + lane];
            #pragma unroll
            for (int off = 16; off > 0; off >>= 1) {
                t1 += __shfl_down_sync(0xffffffffu, t1, off);
                t2 += __shfl_down_sync(0xffffffffu, t2, off);
            }
            if (lane == 0) {
                const float mu = t1 * (1.f / 1024.f);
                s_stats[0] = mu;
                s_stats[1] = rsqrtf(t2 * (1.f / 1024.f) - mu * mu + EPSf);
            }
        }
        __syncthreads();
        o[(size_t)i * Lz] = (v - s_stats[0]) * s_stats[1] * gv + bv;
        c += p[(size_t)i * Lz];
    }
}

// =====================================================================
// Batched per-head SGEMM: C[m,h,n] = [A0 | A1][m,h,:256] @ W[h] + bias[h]
// 128x128 tile, BK=8, 256 threads, 8x8 per thread, double-buffered smem.
// (Proven R1 scalar-FFMA version: 582us for GEMM1, fma=55.6%.)
// =====================================================================
template <int NLD, bool PHASE1>
__global__ __launch_bounds__(256, 2) void k_gemm(const float* __restrict__ A0,
                                                 const float* __restrict__ W,
                                                 const float* __restrict__ bias) {
    const float* __restrict__ A1 = PHASE1 ? g_csum_ln : g_cell;
    float* __restrict__ C = PHASE1 ? g_h3 : g_og;

    const int mt = blockIdx.x, nt = blockIdx.y, h = blockIdx.z;
    const int tid = threadIdx.x;
    const int m0 = mt * 128, n0 = nt * 128;

    __shared__ float As[2][8][128];
    __shared__ float Bs[2][8][128];

    const int am = tid >> 1;            // 0..127 (row in A tile)
    const int ak = (tid & 1) * 4;       // 0 or 4 (k in A tile)
    const int bk = tid >> 5;            // 0..7   (k in B tile)
    const int bn = (tid & 31) * 4;      // 0..124 (n in B tile)

    const float* Wh = W + (size_t)h * 256 * NLD;
    const size_t arow = ((size_t)(m0 + am) * Hz + h) * 128;

    const int tr = (tid >> 4) * 8;
    const int tc = (tid & 15) * 8;

    float acc[8][8];
    #pragma unroll
    for (int i = 0; i < 8; i++)
        #pragma unroll
        for (int j = 0; j < 8; j++) acc[i][j] = 0.f;

    // prefetch k-tile 0 (always from A0)
    {
        float4 a4 = *(const float4*)(A0 + arow + ak);
        float4 b4 = *(const float4*)(Wh + (size_t)bk * NLD + n0 + bn);
        As[0][ak + 0][am] = a4.x;
        As[0][ak + 1][am] = a4.y;
        As[0][ak + 2][am] = a4.z;
        As[0][ak + 3][am] = a4.w;
        *(float4*)(&Bs[0][bk][bn]) = b4;
    }
    __syncthreads();

    #pragma unroll 1
    for (int kt = 0; kt < 32; kt++) {
        const int cur = kt & 1;
        float4 na4, nb4;
        if (kt < 31) {
            const int k2 = kt + 1;
            const float* Asrc = (k2 < 16) ? A0 : A1;
            const int koff = (k2 & 15) * 8;
            na4 = *(const float4*)(Asrc + arow + koff + ak);
            nb4 = *(const float4*)(Wh + (size_t)(k2 * 8 + bk) * NLD + n0 + bn);
        }
        #pragma unroll
        for (int kk = 0; kk < 8; kk++) {
            float a[8], bb[8];
            *(float4*)(a)      = *(const float4*)(&As[cur][kk][tr]);
            *(float4*)(a + 4)  = *(const float4*)(&As[cur][kk][tr + 4]);
            *(float4*)(bb)     = *(const float4*)(&Bs[cur][kk][tc]);
            *(float4*)(bb + 4) = *(const float4*)(&Bs[cur][kk][tc + 4]);
            #pragma unroll
            for (int i = 0; i < 8; i++)
                #pragma unroll
                for (int j = 0; j < 8; j++)
                    acc[i][j] = fmaf(a[i], bb[j], acc[i][j]);
        }
        if (kt < 31) {
            const int nxt = cur ^ 1;
            As[nxt][ak + 0][am] = na4.x;
            As[nxt][ak + 1][am] = na4.y;
            As[nxt][ak + 2][am] = na4.z;
            As[nxt][ak + 3][am] = na4.w;
            *(float4*)(&Bs[nxt][bk][bn]) = nb4;
            __syncthreads();
        }
    }

    float bv[8];
    *(float4*)(bv)     = *(const float4*)(bias + h * NLD + n0 + tc);
    *(float4*)(bv + 4) = *(const float4*)(bias + h * NLD + n0 + tc + 4);
    #pragma unroll
    for (int i = 0; i < 8; i++) {
        const size_t crow = ((size_t)(m0 + tr + i) * Hz + h) * NLD + n0 + tc;
        float4 o1 = make_float4(acc[i][0] + bv[0], acc[i][1] + bv[1],
                                acc[i][2] + bv[2], acc[i][3] + bv[3]);
        float4 o2 = make_float4(acc[i][4] + bv[4], acc[i][5] + bv[5],
                                acc[i][6] + bv[6], acc[i][7] + bv[7]);
        *(float4*)(C + crow)     = o1;
        *(float4*)(C + crow + 4) = o2;
    }
}

// =====================================================================
// Phase 3: LN over (H,3,DO) per (b,s), gates, per-chunk scan composition
// =====================================================================
__global__ void k_gates(const float* __restrict__ gam, const float* __restrict__ bet) {
    __shared__ float row[3072];
    __shared__ float sred[64];
    __shared__ float s_stats[2];
    const int b = blockIdx.x, ch = blockIdx.y, l = threadIdx.x;
    const int wid = l >> 5, lane = l & 31;
    const int h = l >> 7, dd = l & 127;
    const int pb = (h * 3) * 128 + dd;
    const float gi = gam[pb], gf = gam[pb + 128], gh = gam[pb + 256];
    const float bi = bet[pb], bf = bet[pb + 128], bh = bet[pb + 256];
    float F = 1.f, Acc = 0.f;
    for (int i = 0; i < CLEN; i++) {
        const size_t rb = (size_t)(b * Sz + ch * CLEN + i) * (Hz * N1z);
        const float v0 = g_h3[rb + l];
        const float v1 = g_h3[rb + 1024 + l];
        const float v2 = g_h3[rb + 2048 + l];
        row[l] = v0; row[1024 + l] = v1; row[2048 + l] = v2;
        float r1 = v0 + v1 + v2;
        float r2 = v0 * v0 + v1 * v1 + v2 * v2;
        #pragma unroll
        for (int off = 16; off > 0; off >>= 1) {
            r1 += __shfl_down_sync(0xffffffffu, r1, off);
            r2 += __shfl_down_sync(0xffffffffu, r2, off);
        }
        if (lane == 0) { sred[wid] = r1; sred[32 + wid] = r2; }
        __syncthreads();
        if (wid == 0) {
            float t1 = sred[lane], t2 = sred[32 + lane];
            #pragma unroll
            for (int off = 16; off > 0; off >>= 1) {
                t1 += __shfl_down_sync(0xffffffffu, t1, off);
                t2 += __shfl_down_sync(0xffffffffu, t2, off);
            }
            if (lane == 0) {
                const float mu = t1 * (1.f / 3072.f);
                s_stats[0] = mu;
                s_stats[1] = rsqrtf(t2 * (1.f / 3072.f) - mu * mu + EPSf);
            }
        }
        __syncthreads();
        const float mu = s_stats[0], rs = s_stats[1];
        const int base = h * N1z + dd;
        const float xig = (row[base]       - mu) * rs * gi + bi;
        const float xfg = (row[base + 128] - mu) * rs * gf + bf;
        const float xhd = (row[base + 256] - mu) * rs * gh + bh;
        const float f  = 1.f / (1.f + __expf(-xfg));
        const float ii = (1.f / (1.f + __expf(-xig))) * fmaxf(xhd, 0.f);
        g_fgi[(size_t)(b * Sz + ch * CLEN + i) * Lz + l] = make_float2(f, ii);
        Acc = f * Acc + ii;
        F *= f;
        __syncthreads();
    }
    const int ci = (b * NCH + ch) * Lz + l;
    g_chF[ci] = F;
    g_chAcc[ci] = Acc;
}

__global__ void k_carry(const float* __restrict__ init_cx) {
    const int b = blockIdx.x, l = threadIdx.x;
    float c = init_cx[l];
    #pragma unroll 4
    for (int ch = 0; ch < NCH; ch++) {
        const int idx = (b * NCH + ch) * Lz + l;
        g_carry[idx] = c;
        c = g_chF[idx] * c + g_chAcc[idx];
    }
}

__global__ void k_replay() {
    const int b = blockIdx.x, ch = blockIdx.y, l = threadIdx.x;
    float c = g_carry[(b * NCH + ch) * Lz + l];
    const size_t base = (size_t)(b * Sz + ch * CLEN) * Lz + l;
    #pragma unroll 4
    for (int i = 0; i < CLEN; i++) {
        const float2 fi = g_fgi[base + (size_t)i * Lz];
        c = fi.x * c + fi.y;
        g_cell[base + (size_t)i * Lz] = c;
    }
}

// =====================================================================
// Phase 5: LN over (H,DO) per (b,s), sigmoid(og) * cell -> out
// =====================================================================
__global__ void k_final(const float* __restrict__ gam, const float* __restrict__ bet,
                        float* __restrict__ out) {
    __shared__ float sred[16];
    __shared__ float s_stats[2];
    const int bs = blockIdx.x, t = threadIdx.x;
    const int wid = t >> 5, lane = t & 31;
    const size_t base = (size_t)bs * Lz + t * 4;
    const float4 v = *(const float4*)(g_og + base);
    float r1 = v.x + v.y + v.z + v.w;
    float r2 = v.x * v.x + v.y * v.y + v.z * v.z + v.w * v.w;
    #pragma unroll
    for (int off = 16; off > 0; off >>= 1) {
        r1 += __shfl_down_sync(0xffffffffu, r1, off);
        r2 += __shfl_down_sync(0xffffffffu, r2, off);
    }
    if (lane == 0) { sred[wid] = r1; sred[8 + wid] = r2; }
    __syncthreads();
    if (wid == 0) {
        float t1 = lane < 8 ? sred[lane] : 0.f;
        float t2 = lane < 8 ? sred[8 + lane] : 0.f;
        #pragma unroll
        for (int off = 4; off > 0; off >>= 1) {
            t1 += __shfl_down_sync(0xffffffffu, t1, off);
            t2 += __shfl_down_sync(0xffffffffu, t2, off);
        }
        if (lane == 0) {
            const float mu = t1 * (1.f / 1024.f);
            s_stats[0] = mu;
            s_stats[1] = rsqrtf(t2 * (1.f / 1024.f) - mu * mu + EPSf);
        }
    }
    __syncthreads();
    const float mu = s_stats[0], rs = s_stats[1];
    const float4 cc = *(const float4*)(g_cell + base);
    const float4 gg = *(const float4*)(gam + t * 4);
    const float4 bb = *(const float4*)(bet + t * 4);
    float4 o;
    o.x = cc.x / (1.f + __expf(-((v.x - mu) * rs * gg.x + bb.x)));
    o.y = cc.y / (1.f + __expf(-((v.y - mu) * rs * gg.y + bb.y)));
    o.z = cc.z / (1.f + __expf(-((v.z - mu) * rs * gg.z + bb.z)));
    o.w = cc.w / (1.f + __expf(-((v.w - mu) * rs * gg.w + bb.w)));
    *(float4*)(out + base) = o;
}

// =====================================================================
extern "C" void kernel_launch(void* const* d_in, const int* in_sizes, int n_in,
                              void* d_out, int out_size) {
    (void)in_sizes; (void)n_in; (void)out_size;
    const float* x       = (const float*)d_in[0];
    const float* W_hid   = (const float*)d_in[1];
    const float* b_hid   = (const float*)d_in[2];
    const float* g_cs    = (const float*)d_in[3];
    const float* be_cs   = (const float*)d_in[4];
    const float* g_hd    = (const float*)d_in[5];
    const float* be_hd   = (const float*)d_in[6];
    const float* W_og    = (const float*)d_in[7];
    const float* b_og    = (const float*)d_in[8];
    const float* g_ogp   = (const float*)d_in[9];
    const float* be_ogp  = (const float*)d_in[10];
    const float* init_cx = (const float*)d_in[11];
    float* out = (float*)d_out;

    // Phase 1: exclusive cumsum + LN(csum)
    k_scan1_partial<<<dim3(Bz, NCH), 1024>>>(x);
    k_scan1_offsets<<<Bz, 1024>>>();
    k_scan1_ln<<<dim3(Bz, NCH), 1024>>>(x, g_cs, be_cs);

    // Phase 2: h3 = [x | ln(csum)] @ W_hid + b_hid
    k_gemm<N1z, true><<<dim3(Sz * Bz / 128, N1z / 128, Hz), 256>>>(x, W_hid, b_hid);

    // Phase 3: LN(h3), gates, chunk compositions
    k_gates<<<dim3(Bz, NCH), 1024>>>(g_hd, be_hd);

    // Phase 4: recurrent scan c = f*c + i
    k_carry<<<Bz, 1024>>>(init_cx);
    k_replay<<<dim3(Bz, NCH), 1024>>>();

    // Phase 5: og = [x | cell] @ W_og + b_og, LN, sigmoid*cell
    k_gemm<128, false><<<dim3(Sz * Bz / 128, 1, Hz), 256>>>(x, W_og, b_og);
    k_final<<<Bz * Sz, 256>>>(g_ogp, be_ogp, out);
}

// round 6
// speedup vs baseline: 2.2126x; 1.0443x over previous
#include <cuda_runtime.h>

#define Bz   4
#define Sz   4096
#define Hz   8
#define Lz   1024      // H * DI
#define N1z  384       // 3 * DO
#define NCH  128       // chunks over S
#define CLEN 32        // S / NCH
#define EPSf 1e-6f

typedef unsigned long long u64;

__device__ __forceinline__ void ffma2(u64& c, u64 a, u64 b) {
    asm("fma.rn.f32x2 %0, %1, %2, %0;" : "+l"(c) : "l"(a), "l"(b));
}
__device__ __forceinline__ u64 dup2(float v) {
    u64 r;
    asm("mov.b64 %0, {%1, %1};" : "=l"(r) : "f"(v));
    return r;
}

// ---------------- scratch (static device memory; no allocations) ----------------
static __device__ float  g_csum_ln[(size_t)Bz * Sz * Lz];        // 64 MB
static __device__ float  g_h3[(size_t)Bz * Sz * Hz * N1z];       // 192 MB
static __device__ float2 g_fgi[(size_t)Bz * Sz * Lz];            // 128 MB (f, i)
static __device__ float  g_cell[(size_t)Bz * Sz * Lz];           // 64 MB
static __device__ float  g_og[(size_t)Bz * Sz * Lz];             // 64 MB
static __device__ float  g_chA[Bz * NCH * Lz];
static __device__ float  g_chF[Bz * NCH * Lz];
static __device__ float  g_chAcc[Bz * NCH * Lz];
static __device__ float  g_carry[Bz * NCH * Lz];

// =====================================================================
// Phase 1: exclusive cumsum over S + LayerNorm over (H,DI) per (b,s)
// =====================================================================
__global__ void k_scan1_partial(const float* __restrict__ x) {
    const int b = blockIdx.x, ch = blockIdx.y, l = threadIdx.x;
    const float* p = x + (size_t)(b * Sz + ch * CLEN) * Lz + l;
    float s0 = 0.f, s1 = 0.f, s2 = 0.f, s3 = 0.f;
    #pragma unroll
    for (int i = 0; i < CLEN; i += 4) {
        s0 += p[(size_t)(i + 0) * Lz];
        s1 += p[(size_t)(i + 1) * Lz];
        s2 += p[(size_t)(i + 2) * Lz];
        s3 += p[(size_t)(i + 3) * Lz];
    }
    g_chA[(b * NCH + ch) * Lz + l] = (s0 + s1) + (s2 + s3);
}

__global__ void k_scan1_offsets() {
    const int b = blockIdx.x, l = threadIdx.x;
    float run = 0.f;
    #pragma unroll 4
    for (int ch = 0; ch < NCH; ch++) {
        const int idx = (b * NCH + ch) * Lz + l;
        const float t = g_chA[idx];
        g_chA[idx] = run;
        run += t;
    }
}

__global__ void k_scan1_ln(const float* __restrict__ x,
                           const float* __restrict__ gam,
                           const float* __restrict__ bet) {
    __shared__ float sred[64];
    __shared__ float s_stats[2];
    const int b = blockIdx.x, ch = blockIdx.y, l = threadIdx.x;
    const int wid = l >> 5, lane = l & 31;
    float c = g_chA[(b * NCH + ch) * Lz + l];
    const float gv = gam[l], bv = bet[l];
    const float* p = x + (size_t)(b * Sz + ch * CLEN) * Lz + l;
    float* o = g_csum_ln + (size_t)(b * Sz + ch * CLEN) * Lz + l;
    for (int i = 0; i < CLEN; i++) {
        const float v = c;
        float r1 = v, r2 = v * v;
        #pragma unroll
        for (int off = 16; off > 0; off >>= 1) {
            r1 += __shfl_down_sync(0xffffffffu, r1, off);
            r2 += __shfl_down_sync(0xffffffffu, r2, off);
        }
        if (lane == 0) { sred[wid] = r1; sred[32 + wid] = r2; }
        __syncthreads();
        if (wid == 0) {
            float t1 = sred[lane], t2 = sred[32 + lane];
            #pragma unroll
            for (int off = 16; off > 0; off >>= 1) {
                t1 += __shfl_down_sync(0xffffffffu, t1, off);
                t2 += __shfl_down_sync(0xffffffffu, t2, off);
            }
            if (lane == 0) {
                const float mu = t1 * (1.f / 1024.f);
                s_stats[0] = mu;
                s_stats[1] = rsqrtf(t2 * (1.f / 1024.f) - mu * mu + EPSf);
            }
        }
        __syncthreads();
        o[(size_t)i * Lz] = (v - s_stats[0]) * s_stats[1] * gv + bv;
        c += p[(size_t)i * Lz];
    }
}

// =====================================================================
// Batched per-head SGEMM via fma.rn.f32x2 (dual-rate fp32 pipe).
// 128x128 tile, BK=8, 256 threads, 8x8 per thread.
// Column-paired accumulators: B pairs come free from contiguous smem,
// A is duplicated in registers (2 extra regs live). Smem layout is
// IDENTICAL to the proven scalar version (no extra LDS, no spills).
// =====================================================================
template <int NLD, bool PHASE1>
__global__ __launch_bounds__(256, 2) void k_gemm(const float* __restrict__ A0,
                                                 const float* __restrict__ W,
                                                 const float* __restrict__ bias) {
    const float* __restrict__ A1 = PHASE1 ? g_csum_ln : g_cell;
    float* __restrict__ C = PHASE1 ? g_h3 : g_og;

    const int mt = blockIdx.x, nt = blockIdx.y, h = blockIdx.z;
    const int tid = threadIdx.x;
    const int m0 = mt * 128, n0 = nt * 128;

    __shared__ float As[2][8][128];
    __shared__ float Bs[2][8][128];

    const int am = tid >> 1;            // 0..127 (row in A tile)
    const int ak = (tid & 1) * 4;       // 0 or 4 (k in A tile)
    const int bk = tid >> 5;            // 0..7   (k in B tile)
    const int bn = (tid & 31) * 4;      // 0..124 (n in B tile)

    const float* Wh = W + (size_t)h * 256 * NLD;
    const size_t arow = ((size_t)(m0 + am) * Hz + h) * 128;

    const int tr = (tid >> 4) * 8;
    const int tc = (tid & 15) * 8;

    // acc2[i][jp] accumulates (row tr+i, cols tc+2jp, tc+2jp+1) as packed f32x2
    u64 acc2[8][4];
    #pragma unroll
    for (int i = 0; i < 8; i++)
        #pragma unroll
        for (int jp = 0; jp < 4; jp++) acc2[i][jp] = 0ull;

    // prefetch k-tile 0 (always from A0)
    {
        float4 a4 = *(const float4*)(A0 + arow + ak);
        float4 b4 = *(const float4*)(Wh + (size_t)bk * NLD + n0 + bn);
        As[0][ak + 0][am] = a4.x;
        As[0][ak + 1][am] = a4.y;
        As[0][ak + 2][am] = a4.z;
        As[0][ak + 3][am] = a4.w;
        *(float4*)(&Bs[0][bk][bn]) = b4;
    }
    __syncthreads();

    #pragma unroll 1
    for (int kt = 0; kt < 32; kt++) {
        const int cur = kt & 1;
        float4 na4, nb4;
        if (kt < 31) {
            const int k2 = kt + 1;
            const float* Asrc = (k2 < 16) ? A0 : A1;
            const int koff = (k2 & 15) * 8;
            na4 = *(const float4*)(Asrc + arow + koff + ak);
            nb4 = *(const float4*)(Wh + (size_t)(k2 * 8 + bk) * NLD + n0 + bn);
        }
        #pragma unroll
        for (int kk = 0; kk < 8; kk++) {
            float a[8];
            *(float4*)(a)      = *(const float4*)(&As[cur][kk][tr]);
            *(float4*)(a + 4)  = *(const float4*)(&As[cur][kk][tr + 4]);
            u64 bp[4];
            *(float4*)(bp)     = *(const float4*)(&Bs[cur][kk][tc]);       // bp[0], bp[1]
            *(float4*)(bp + 2) = *(const float4*)(&Bs[cur][kk][tc + 4]);   // bp[2], bp[3]
            #pragma unroll
            for (int i = 0; i < 8; i++) {
                const u64 da = dup2(a[i]);
                ffma2(acc2[i][0], da, bp[0]);
                ffma2(acc2[i][1], da, bp[1]);
                ffma2(acc2[i][2], da, bp[2]);
                ffma2(acc2[i][3], da, bp[3]);
            }
        }
        if (kt < 31) {
            const int nxt = cur ^ 1;
            As[nxt][ak + 0][am] = na4.x;
            As[nxt][ak + 1][am] = na4.y;
            As[nxt][ak + 2][am] = na4.z;
            As[nxt][ak + 3][am] = na4.w;
            *(float4*)(&Bs[nxt][bk][bn]) = nb4;
            __syncthreads();
        }
    }

    float bv[8];
    *(float4*)(bv)     = *(const float4*)(bias + h * NLD + n0 + tc);
    *(float4*)(bv + 4) = *(const float4*)(bias + h * NLD + n0 + tc + 4);
    #pragma unroll
    for (int i = 0; i < 8; i++) {
        const size_t crow = ((size_t)(m0 + tr + i) * Hz + h) * NLD + n0 + tc;
        float o[8];
        #pragma unroll
        for (int jp = 0; jp < 4; jp++) {
            const float2 p = *(const float2*)(&acc2[i][jp]);
            o[2 * jp]     = p.x + bv[2 * jp];
            o[2 * jp + 1] = p.y + bv[2 * jp + 1];
        }
        *(float4*)(C + crow)     = *(float4*)(o);
        *(float4*)(C + crow + 4) = *(float4*)(o + 4);
    }
}

// =====================================================================
// Phase 3: LN over (H,3,DO) per (b,s), gates, per-chunk scan composition
// =====================================================================
__global__ void k_gates(const float* __restrict__ gam, const float* __restrict__ bet) {
    __shared__ float row[3072];
    __shared__ float sred[64];
    __shared__ float s_stats[2];
    const int b = blockIdx.x, ch = blockIdx.y, l = threadIdx.x;
    const int wid = l >> 5, lane = l & 31;
    const int h = l >> 7, dd = l & 127;
    const int pb = (h * 3) * 128 + dd;
    const float gi = gam[pb], gf = gam[pb + 128], gh = gam[pb + 256];
    const float bi = bet[pb], bf = bet[pb + 128], bh = bet[pb + 256];
    float F = 1.f, Acc = 0.f;
    for (int i = 0; i < CLEN; i++) {
        const size_t rb = (size_t)(b * Sz + ch * CLEN + i) * (Hz * N1z);
        const float v0 = g_h3[rb + l];
        const float v1 = g_h3[rb + 1024 + l];
        const float v2 = g_h3[rb + 2048 + l];
        row[l] = v0; row[1024 + l] = v1; row[2048 + l] = v2;
        float r1 = v0 + v1 + v2;
        float r2 = v0 * v0 + v1 * v1 + v2 * v2;
        #pragma unroll
        for (int off = 16; off > 0; off >>= 1) {
            r1 += __shfl_down_sync(0xffffffffu, r1, off);
            r2 += __shfl_down_sync(0xffffffffu, r2, off);
        }
        if (lane == 0) { sred[wid] = r1; sred[32 + wid] = r2; }
        __syncthreads();
        if (wid == 0) {
            float t1 = sred[lane], t2 = sred[32 + lane];
            #pragma unroll
            for (int off = 16; off > 0; off >>= 1) {
                t1 += __shfl_down_sync(0xffffffffu, t1, off);
                t2 += __shfl_down_sync(0xffffffffu, t2, off);
            }
            if (lane == 0) {
                const float mu = t1 * (1.f / 3072.f);
                s_stats[0] = mu;
                s_stats[1] = rsqrtf(t2 * (1.f / 3072.f) - mu * mu + EPSf);
            }
        }
        __syncthreads();
        const float mu = s_stats[0], rs = s_stats[1];
        const int base = h * N1z + dd;
        const float xig = (row[base]       - mu) * rs * gi + bi;
        const float xfg = (row[base + 128] - mu) * rs * gf + bf;
        const float xhd = (row[base + 256] - mu) * rs * gh + bh;
        const float f  = 1.f / (1.f + __expf(-xfg));
        const float ii = (1.f / (1.f + __expf(-xig))) * fmaxf(xhd, 0.f);
        g_fgi[(size_t)(b * Sz + ch * CLEN + i) * Lz + l] = make_float2(f, ii);
        Acc = f * Acc + ii;
        F *= f;
        __syncthreads();
    }
    const int ci = (b * NCH + ch) * Lz + l;
    g_chF[ci] = F;
    g_chAcc[ci] = Acc;
}

__global__ void k_carry(const float* __restrict__ init_cx) {
    const int b = blockIdx.x, l = threadIdx.x;
    float c = init_cx[l];
    #pragma unroll 4
    for (int ch = 0; ch < NCH; ch++) {
        const int idx = (b * NCH + ch) * Lz + l;
        g_carry[idx] = c;
        c = g_chF[idx] * c + g_chAcc[idx];
    }
}

__global__ void k_replay() {
    const int b = blockIdx.x, ch = blockIdx.y, l = threadIdx.x;
    float c = g_carry[(b * NCH + ch) * Lz + l];
    const size_t base = (size_t)(b * Sz + ch * CLEN) * Lz + l;
    #pragma unroll 4
    for (int i = 0; i < CLEN; i++) {
        const float2 fi = g_fgi[base + (size_t)i * Lz];
        c = fi.x * c + fi.y;
        g_cell[base + (size_t)i * Lz] = c;
    }
}

// =====================================================================
// Phase 5: LN over (H,DO) per (b,s), sigmoid(og) * cell -> out
// =====================================================================
__global__ void k_final(const float* __restrict__ gam, const float* __restrict__ bet,
                        float* __restrict__ out) {
    __shared__ float sred[16];
    __shared__ float s_stats[2];
    const int bs = blockIdx.x, t = threadIdx.x;
    const int wid = t >> 5, lane = t & 31;
    const size_t base = (size_t)bs * Lz + t * 4;
    const float4 v = *(const float4*)(g_og + base);
    float r1 = v.x + v.y + v.z + v.w;
    float r2 = v.x * v.x + v.y * v.y + v.z * v.z + v.w * v.w;
    #pragma unroll
    for (int off = 16; off > 0; off >>= 1) {
        r1 += __shfl_down_sync(0xffffffffu, r1, off);
        r2 += __shfl_down_sync(0xffffffffu, r2, off);
    }
    if (lane == 0) { sred[wid] = r1; sred[8 + wid] = r2; }
    __syncthreads();
    if (wid == 0) {
        float t1 = lane < 8 ? sred[lane] : 0.f;
        float t2 = lane < 8 ? sred[8 + lane] : 0.f;
        #pragma unroll
        for (int off = 4; off > 0; off >>= 1) {
            t1 += __shfl_down_sync(0xffffffffu, t1, off);
            t2 += __shfl_down_sync(0xffffffffu, t2, off);
        }
        if (lane == 0) {
            const float mu = t1 * (1.f / 1024.f);
            s_stats[0] = mu;
            s_stats[1] = rsqrtf(t2 * (1.f / 1024.f) - mu * mu + EPSf);
        }
    }
    __syncthreads();
    const float mu = s_stats[0], rs = s_stats[1];
    const float4 cc = *(const float4*)(g_cell + base);
    const float4 gg = *(const float4*)(gam + t * 4);
    const float4 bb = *(const float4*)(bet + t * 4);
    float4 o;
    o.x = cc.x / (1.f + __expf(-((v.x - mu) * rs * gg.x + bb.x)));
    o.y = cc.y / (1.f + __expf(-((v.y - mu) * rs * gg.y + bb.y)));
    o.z = cc.z / (1.f + __expf(-((v.z - mu) * rs * gg.z + bb.z)));
    o.w = cc.w / (1.f + __expf(-((v.w - mu) * rs * gg.w + bb.w)));
    *(float4*)(out + base) = o;
}

// =====================================================================
extern "C" void kernel_launch(void* const* d_in, const int* in_sizes, int n_in,
                              void* d_out, int out_size) {
    (void)in_sizes; (void)n_in; (void)out_size;
    const float* x       = (const float*)d_in[0];
    const float* W_hid   = (const float*)d_in[1];
    const float* b_hid   = (const float*)d_in[2];
    const float* g_cs    = (const float*)d_in[3];
    const float* be_cs   = (const float*)d_in[4];
    const float* g_hd    = (const float*)d_in[5];
    const float* be_hd   = (const float*)d_in[6];
    const float* W_og    = (const float*)d_in[7];
    const float* b_og    = (const float*)d_in[8];
    const float* g_ogp   = (const float*)d_in[9];
    const float* be_ogp  = (const float*)d_in[10];
    const float* init_cx = (const float*)d_in[11];
    float* out = (float*)d_out;

    // Phase 1: exclusive cumsum + LN(csum)
    k_scan1_partial<<<dim3(Bz, NCH), 1024>>>(x);
    k_scan1_offsets<<<Bz, 1024>>>();
    k_scan1_ln<<<dim3(Bz, NCH), 1024>>>(x, g_cs, be_cs);

    // Phase 2: h3 = [x | ln(csum)] @ W_hid + b_hid
    k_gemm<N1z, true><<<dim3(Sz * Bz / 128, N1z / 128, Hz), 256>>>(x, W_hid, b_hid);

    // Phase 3: LN(h3), gates, chunk compositions
    k_gates<<<dim3(Bz, NCH), 1024>>>(g_hd, be_hd);

    // Phase 4: recurrent scan c = f*c + i
    k_carry<<<Bz, 1024>>>(init_cx);
    k_replay<<<dim3(Bz, NCH), 1024>>>();

    // Phase 5: og = [x | cell] @ W_og + b_og, LN, sigmoid*cell
    k_gemm<128, false><<<dim3(Sz * Bz / 128, 1, Hz), 256>>>(x, W_og, b_og);
    k_final<<<Bz * Sz, 256>>>(g_ogp, be_ogp, out);
}

// round 8
// speedup vs baseline: 2.9144x; 1.3172x over previous
#include <cuda_runtime.h>
#include <cuda_bf16.h>
#include <cstdint>

#define Bz   4
#define Sz   4096
#define Hz   8
#define Lz   1024      // H * DI
#define N1z  384       // 3 * DO
#define NCH  128       // chunks over S
#define CLEN 32        // S / NCH
#define EPSf 1e-6f

typedef unsigned long long u64;

// ---------------- scratch (static device memory; no allocations) ----------------
static __device__ float  g_csum_ln[(size_t)Bz * Sz * Lz];        // 64 MB
static __device__ float  g_h3[(size_t)Bz * Sz * Hz * N1z];       // 192 MB
static __device__ float2 g_fgi[(size_t)Bz * Sz * Lz];            // 128 MB (f, i)
static __device__ float  g_cell[(size_t)Bz * Sz * Lz];           // 64 MB
static __device__ float  g_og[(size_t)Bz * Sz * Lz];             // 64 MB
static __device__ float  g_chA[Bz * NCH * Lz];
static __device__ float  g_chF[Bz * NCH * Lz];
static __device__ float  g_chAcc[Bz * NCH * Lz];
static __device__ float  g_carry[Bz * NCH * Lz];
// split-bf16 weights, transposed to [h][n][k=256]
static __device__ __nv_bfloat16 g_Whid_hi[Hz * N1z * 256];
static __device__ __nv_bfloat16 g_Whid_lo[Hz * N1z * 256];
static __device__ __nv_bfloat16 g_Wog_hi[Hz * 128 * 256];
static __device__ __nv_bfloat16 g_Wog_lo[Hz * 128 * 256];

// ========================= mma.sync helpers ==========================
__device__ __forceinline__ uint32_t smem_u32(const void* p) {
    uint32_t a;
    asm("{ .reg .u64 t; cvta.to.shared.u64 t, %1; cvt.u32.u64 %0, t; }"
        : "=r"(a) : "l"(p));
    return a;
}
__device__ __forceinline__ void ldsm4(uint32_t* r, uint32_t addr) {
    asm volatile("ldmatrix.sync.aligned.m8n8.x4.shared.b16 {%0,%1,%2,%3}, [%4];"
        : "=r"(r[0]), "=r"(r[1]), "=r"(r[2]), "=r"(r[3]) : "r"(addr));
}
__device__ __forceinline__ void mma16816(float* c, const uint32_t* a, const uint32_t* b) {
    asm volatile(
        "mma.sync.aligned.m16n8k16.row.col.f32.bf16.bf16.f32 "
        "{%0,%1,%2,%3}, {%4,%5,%6,%7}, {%8,%9}, {%0,%1,%2,%3};"
        : "+f"(c[0]), "+f"(c[1]), "+f"(c[2]), "+f"(c[3])
        : "r"(a[0]), "r"(a[1]), "r"(a[2]), "r"(a[3]), "r"(b[0]), "r"(b[1]));
}
__device__ __forceinline__ uint32_t swz(uint32_t o) { return o ^ ((o >> 3) & 0x70); }
__device__ __forceinline__ uint32_t pack_bf(__nv_bfloat16 a, __nv_bfloat16 b) {
    __nv_bfloat162 t(a, b);
    return *reinterpret_cast<uint32_t*>(&t);
}

// smem layout (dynamic): 4 x 16KB bf16 tiles (128 rows x 64 cols, 128B rows, swizzled)
#define SM_AHI 0
#define SM_ALO 16384
#define SM_BHI 32768
#define SM_BLO 49152
#define SM_TOT 65536

// =====================================================================
// Weight conversion: W [h][k=256][N] fp32 -> hi/lo bf16 [h][n][k=256]
// =====================================================================
__global__ void k_wconv(const float* __restrict__ W,
                        __nv_bfloat16* __restrict__ hi,
                        __nv_bfloat16* __restrict__ lo, int N) {
    const int idx = blockIdx.x * blockDim.x + threadIdx.x;
    if (idx >= Hz * 256 * N) return;
    const int h = idx / (256 * N);
    const int r = idx % (256 * N);
    const int k = r / N;
    const int n = r % N;
    const float v = W[idx];
    const __nv_bfloat16 vh = __float2bfloat16(v);
    const __nv_bfloat16 vl = __float2bfloat16(v - __bfloat162float(vh));
    const size_t o = ((size_t)h * N + n) * 256 + k;
    hi[o] = vh;
    lo[o] = vl;
}

// =====================================================================
// Tensor-core batched per-head GEMM, 3-term bf16 split, mma.sync HMMA.
// C[m, h, n] = [A0 | A1][m, h, :256] @ W[h] + bias[h]
// CTA tile 128x128, 8 warps (4m x 2n), warp tile 32x64.
// =====================================================================
template <int NLD, bool PHASE1>
__global__ __launch_bounds__(256) void k_gemm_mma(const float* __restrict__ A0,
                                                  const __nv_bfloat16* __restrict__ Bhi,
                                                  const __nv_bfloat16* __restrict__ Blo,
                                                  const float* __restrict__ bias) {
    const float* __restrict__ A1 = PHASE1 ? g_csum_ln : g_cell;
    float* __restrict__ C = PHASE1 ? g_h3 : g_og;

    extern __shared__ char sm[];
    const uint32_t sb = smem_u32(sm);
    const int tid = threadIdx.x;
    const int lane = tid & 31, wid = tid >> 5;
    const int m0 = blockIdx.x * 128, n0 = blockIdx.y * 128, h = blockIdx.z;
    const int wm = (wid & 3) * 32;      // warp row base in tile
    const int wn = (wid >> 2) * 64;     // warp col base in tile

    float acc[2][8][4];
    #pragma unroll
    for (int mt = 0; mt < 2; mt++)
        #pragma unroll
        for (int nt = 0; nt < 8; nt++)
            #pragma unroll
            for (int q = 0; q < 4; q++) acc[mt][nt][q] = 0.f;

    // ldmatrix per-lane row/byte offsets
    // A quads: (m0-7,k0-7),(m8-15,k0-7),(m0-7,k8-15),(m8-15,k8-15)
    const int aq = lane >> 3;
    const int arow_l = (aq & 1) * 8 + (lane & 7);
    const int akb    = (aq >> 1) * 16;
    // B quads: (n0-7,k0-7),(n0-7,k8-15),(n8-15,k0-7),(n8-15,k8-15)
    const int brow_l = (aq >> 1) * 8 + (lane & 7);
    const int bkb    = (aq & 1) * 16;

    #pragma unroll 1
    for (int c = 0; c < 4; c++) {
        if (c) __syncthreads();
        // ---- stage A chunk: fp32 -> hi/lo bf16, swizzled [row][64] ----
        {
            const float* Asrc = (c < 2) ? A0 : A1;
            const int kb = (c & 1) * 64;
            const int col = (tid & 15) * 4;
            #pragma unroll
            for (int j = 0; j < 8; j++) {
                const int row = (tid >> 4) + j * 16;
                const float4 v = *(const float4*)(Asrc +
                    ((size_t)(m0 + row) * Hz + h) * 128 + kb + col);
                const __nv_bfloat16 h0 = __float2bfloat16(v.x);
                const __nv_bfloat16 h1 = __float2bfloat16(v.y);
                const __nv_bfloat16 h2 = __float2bfloat16(v.z);
                const __nv_bfloat16 h3 = __float2bfloat16(v.w);
                const __nv_bfloat16 l0 = __float2bfloat16(v.x - __bfloat162float(h0));
                const __nv_bfloat16 l1 = __float2bfloat16(v.y - __bfloat162float(h1));
                const __nv_bfloat16 l2 = __float2bfloat16(v.z - __bfloat162float(h2));
                const __nv_bfloat16 l3 = __float2bfloat16(v.w - __bfloat162float(h3));
                const uint32_t so = swz((uint32_t)(row * 128 + col * 2));
                *(uint2*)(sm + SM_AHI + so) = make_uint2(pack_bf(h0, h1), pack_bf(h2, h3));
                *(uint2*)(sm + SM_ALO + so) = make_uint2(pack_bf(l0, l1), pack_bf(l2, l3));
            }
        }
        // ---- stage B chunk: preconverted bf16 [h][n][k], swizzled [n][64] ----
        {
            const int q = tid & 7;
            #pragma unroll
            for (int j = 0; j < 4; j++) {
                const int n = (tid >> 3) + j * 32;
                const size_t goff = ((size_t)(h * NLD + n0 + n) * 256 + c * 64);
                const uint4 vh = ((const uint4*)(Bhi + goff))[q];
                const uint4 vl = ((const uint4*)(Blo + goff))[q];
                const uint32_t so = swz((uint32_t)(n * 128 + q * 16));
                *(uint4*)(sm + SM_BHI + so) = vh;
                *(uint4*)(sm + SM_BLO + so) = vl;
            }
        }
        __syncthreads();

        #pragma unroll
        for (int k16 = 0; k16 < 4; k16++) {
            uint32_t ahi[2][4], alo[2][4];
            #pragma unroll
            for (int mt = 0; mt < 2; mt++) {
                const uint32_t off =
                    swz((uint32_t)((wm + mt * 16 + arow_l) * 128 + k16 * 32 + akb));
                ldsm4(ahi[mt], sb + SM_AHI + off);
                ldsm4(alo[mt], sb + SM_ALO + off);
            }
            #pragma unroll
            for (int np = 0; np < 4; np++) {
                uint32_t bhi[4], blo[4];
                const uint32_t off =
                    swz((uint32_t)((wn + np * 16 + brow_l) * 128 + k16 * 32 + bkb));
                ldsm4(bhi, sb + SM_BHI + off);
                ldsm4(blo, sb + SM_BLO + off);
                #pragma unroll
                for (int mt = 0; mt < 2; mt++) {
                    mma16816(acc[mt][np * 2],     ahi[mt], bhi);
                    mma16816(acc[mt][np * 2],     alo[mt], bhi);
                    mma16816(acc[mt][np * 2],     ahi[mt], blo);
                    mma16816(acc[mt][np * 2 + 1], ahi[mt], bhi + 2);
                    mma16816(acc[mt][np * 2 + 1], alo[mt], bhi + 2);
                    mma16816(acc[mt][np * 2 + 1], ahi[mt], blo + 2);
                }
            }
        }
    }

    // ---- epilogue: acc regs -> C (+bias), fragment layout stores ----
    #pragma unroll
    for (int mt = 0; mt < 2; mt++) {
        const int r0 = m0 + wm + mt * 16 + (lane >> 2);
        #pragma unroll
        for (int nt = 0; nt < 8; nt++) {
            const int col = n0 + wn + nt * 8 + (lane & 3) * 2;
            const float2 bv = *(const float2*)(bias + h * NLD + col);
            float2 o0, o1;
            o0.x = acc[mt][nt][0] + bv.x;  o0.y = acc[mt][nt][1] + bv.y;
            o1.x = acc[mt][nt][2] + bv.x;  o1.y = acc[mt][nt][3] + bv.y;
            *(float2*)(C + ((size_t)r0 * Hz + h) * NLD + col)       = o0;
            *(float2*)(C + ((size_t)(r0 + 8) * Hz + h) * NLD + col) = o1;
        }
    }
}

// =====================================================================
// Phase 1: exclusive cumsum over S + LayerNorm over (H,DI) per (b,s)
// =====================================================================
__global__ void k_scan1_partial(const float* __restrict__ x) {
    const int b = blockIdx.x, ch = blockIdx.y, l = threadIdx.x;
    const float* p = x + (size_t)(b * Sz + ch * CLEN) * Lz + l;
    float s0 = 0.f, s1 = 0.f, s2 = 0.f, s3 = 0.f;
    #pragma unroll
    for (int i = 0; i < CLEN; i += 4) {
        s0 += p[(size_t)(i + 0) * Lz];
        s1 += p[(size_t)(i + 1) * Lz];
        s2 += p[(size_t)(i + 2) * Lz];
        s3 += p[(size_t)(i + 3) * Lz];
    }
    g_chA[(b * NCH + ch) * Lz + l] = (s0 + s1) + (s2 + s3);
}

__global__ void k_scan1_offsets() {
    const int b = blockIdx.x, l = threadIdx.x;
    float run = 0.f;
    #pragma unroll 4
    for (int ch = 0; ch < NCH; ch++) {
        const int idx = (b * NCH + ch) * Lz + l;
        const float t = g_chA[idx];
        g_chA[idx] = run;
        run += t;
    }
}

__global__ void k_scan1_ln(const float* __restrict__ x,
                           const float* __restrict__ gam,
                           const float* __restrict__ bet) {
    __shared__ float sred[64];
    __shared__ float s_stats[2];
    const int b = blockIdx.x, ch = blockIdx.y, l = threadIdx.x;
    const int wid = l >> 5, lane = l & 31;
    float c = g_chA[(b * NCH + ch) * Lz + l];
    const float gv = gam[l], bv = bet[l];
    const float* p = x + (size_t)(b * Sz + ch * CLEN) * Lz + l;
    float* o = g_csum_ln + (size_t)(b * Sz + ch * CLEN) * Lz + l;
    for (int i = 0; i < CLEN; i++) {
        const float v = c;
        float r1 = v, r2 = v * v;
        #pragma unroll
        for (int off = 16; off > 0; off >>= 1) {
            r1 += __shfl_down_sync(0xffffffffu, r1, off);
            r2 += __shfl_down_sync(0xffffffffu, r2, off);
        }
        if (lane == 0) { sred[wid] = r1; sred[32 + wid] = r2; }
        __syncthreads();
        if (wid == 0) {
            float t1 = sred[lane], t2 = sred[32 + lane];
            #pragma unroll
            for (int off = 16; off > 0; off >>= 1) {
                t1 += __shfl_down_sync(0xffffffffu, t1, off);
                t2 += __shfl_down_sync(0xffffffffu, t2, off);
            }
            if (lane == 0) {
                const float mu = t1 * (1.f / 1024.f);
                s_stats[0] = mu;
                s_stats[1] = rsqrtf(t2 * (1.f / 1024.f) - mu * mu + EPSf);
            }
        }
        __syncthreads();
        o[(size_t)i * Lz] = (v - s_stats[0]) * s_stats[1] * gv + bv;
        c += p[(size_t)i * Lz];
    }
}

// =====================================================================
// Phase 3: LN over (H,3,DO) per (b,s), gates, per-chunk scan composition
// =====================================================================
__global__ void k_gates(const float* __restrict__ gam, const float* __restrict__ bet) {
    __shared__ float row[3072];
    __shared__ float sred[64];
    __shared__ float s_stats[2];
    const int b = blockIdx.x, ch = blockIdx.y, l = threadIdx.x;
    const int wid = l >> 5, lane = l & 31;
    const int h = l >> 7, dd = l & 127;
    const int pb = (h * 3) * 128 + dd;
    const float gi = gam[pb], gf = gam[pb + 128], gh = gam[pb + 256];
    const float bi = bet[pb], bf = bet[pb + 128], bh = bet[pb + 256];
    float F = 1.f, Acc = 0.f;
    for (int i = 0; i < CLEN; i++) {
        const size_t rb = (size_t)(b * Sz + ch * CLEN + i) * (Hz * N1z);
        const float v0 = g_h3[rb + l];
        const float v1 = g_h3[rb + 1024 + l];
        const float v2 = g_h3[rb + 2048 + l];
        row[l] = v0; row[1024 + l] = v1; row[2048 + l] = v2;
        float r1 = v0 + v1 + v2;
        float r2 = v0 * v0 + v1 * v1 + v2 * v2;
        #pragma unroll
        for (int off = 16; off > 0; off >>= 1) {
            r1 += __shfl_down_sync(0xffffffffu, r1, off);
            r2 += __shfl_down_sync(0xffffffffu, r2, off);
        }
        if (lane == 0) { sred[wid] = r1; sred[32 + wid] = r2; }
        __syncthreads();
        if (wid == 0) {
            float t1 = sred[lane], t2 = sred[32 + lane];
            #pragma unroll
            for (int off = 16; off > 0; off >>= 1) {
                t1 += __shfl_down_sync(0xffffffffu, t1, off);
                t2 += __shfl_down_sync(0xffffffffu, t2, off);
            }
            if (lane == 0) {
                const float mu = t1 * (1.f / 3072.f);
                s_stats[0] = mu;
                s_stats[1] = rsqrtf(t2 * (1.f / 3072.f) - mu * mu + EPSf);
            }
        }
        __syncthreads();
        const float mu = s_stats[0], rs = s_stats[1];
        const int base = h * N1z + dd;
        const float xig = (row[base]       - mu) * rs * gi + bi;
        const float xfg = (row[base + 128] - mu) * rs * gf + bf;
        const float xhd = (row[base + 256] - mu) * rs * gh + bh;
        const float f  = 1.f / (1.f + __expf(-xfg));
        const float ii = (1.f / (1.f + __expf(-xig))) * fmaxf(xhd, 0.f);
        g_fgi[(size_t)(b * Sz + ch * CLEN + i) * Lz + l] = make_float2(f, ii);
        Acc = f * Acc + ii;
        F *= f;
        __syncthreads();
    }
    const int ci = (b * NCH + ch) * Lz + l;
    g_chF[ci] = F;
    g_chAcc[ci] = Acc;
}

__global__ void k_carry(const float* __restrict__ init_cx) {
    const int b = blockIdx.x, l = threadIdx.x;
    float c = init_cx[l];
    #pragma unroll 4
    for (int ch = 0; ch < NCH; ch++) {
        const int idx = (b * NCH + ch) * Lz + l;
        g_carry[idx] = c;
        c = g_chF[idx] * c + g_chAcc[idx];
    }
}

__global__ void k_replay() {
    const int b = blockIdx.x, ch = blockIdx.y, l = threadIdx.x;
    float c = g_carry[(b * NCH + ch) * Lz + l];
    const size_t base = (size_t)(b * Sz + ch * CLEN) * Lz + l;
    #pragma unroll 4
    for (int i = 0; i < CLEN; i++) {
        const float2 fi = g_fgi[base + (size_t)i * Lz];
        c = fi.x * c + fi.y;
        g_cell[base + (size_t)i * Lz] = c;
    }
}

// =====================================================================
// Phase 5: LN over (H,DO) per (b,s), sigmoid(og) * cell -> out
// =====================================================================
__global__ void k_final(const float* __restrict__ gam, const float* __restrict__ bet,
                        float* __restrict__ out) {
    __shared__ float sred[16];
    __shared__ float s_stats[2];
    const int bs = blockIdx.x, t = threadIdx.x;
    const int wid = t >> 5, lane = t & 31;
    const size_t base = (size_t)bs * Lz + t * 4;
    const float4 v = *(const float4*)(g_og + base);
    float r1 = v.x + v.y + v.z + v.w;
    float r2 = v.x * v.x + v.y * v.y + v.z * v.z + v.w * v.w;
    #pragma unroll
    for (int off = 16; off > 0; off >>= 1) {
        r1 += __shfl_down_sync(0xffffffffu, r1, off);
        r2 += __shfl_down_sync(0xffffffffu, r2, off);
    }
    if (lane == 0) { sred[wid] = r1; sred[8 + wid] = r2; }
    __syncthreads();
    if (wid == 0) {
        float t1 = lane < 8 ? sred[lane] : 0.f;
        float t2 = lane < 8 ? sred[8 + lane] : 0.f;
        #pragma unroll
        for (int off = 4; off > 0; off >>= 1) {
            t1 += __shfl_down_sync(0xffffffffu, t1, off);
            t2 += __shfl_down_sync(0xffffffffu, t2, off);
        }
        if (lane == 0) {
            const float mu = t1 * (1.f / 1024.f);
            s_stats[0] = mu;
            s_stats[1] = rsqrtf(t2 * (1.f / 1024.f) - mu * mu + EPSf);
        }
    }
    __syncthreads();
    const float mu = s_stats[0], rs = s_stats[1];
    const float4 cc = *(const float4*)(g_cell + base);
    const float4 gg = *(const float4*)(gam + t * 4);
    const float4 bb = *(const float4*)(bet + t * 4);
    float4 o;
    o.x = cc.x / (1.f + __expf(-((v.x - mu) * rs * gg.x + bb.x)));
    o.y = cc.y / (1.f + __expf(-((v.y - mu) * rs * gg.y + bb.y)));
    o.z = cc.z / (1.f + __expf(-((v.z - mu) * rs * gg.z + bb.z)));
    o.w = cc.w / (1.f + __expf(-((v.w - mu) * rs * gg.w + bb.w)));
    *(float4*)(out + base) = o;
}

// =====================================================================
extern "C" void kernel_launch(void* const* d_in, const int* in_sizes, int n_in,
                              void* d_out, int out_size) {
    (void)in_sizes; (void)n_in; (void)out_size;
    const float* x       = (const float*)d_in[0];
    const float* W_hid   = (const float*)d_in[1];
    const float* b_hid   = (const float*)d_in[2];
    const float* g_cs    = (const float*)d_in[3];
    const float* be_cs   = (const float*)d_in[4];
    const float* g_hd    = (const float*)d_in[5];
    const float* be_hd   = (const float*)d_in[6];
    const float* W_og    = (const float*)d_in[7];
    const float* b_og    = (const float*)d_in[8];
    const float* g_ogp   = (const float*)d_in[9];
    const float* be_ogp  = (const float*)d_in[10];
    const float* init_cx = (const float*)d_in[11];
    float* out = (float*)d_out;

    cudaFuncSetAttribute(k_gemm_mma<N1z, true>,
                         cudaFuncAttributeMaxDynamicSharedMemorySize, SM_TOT);
    cudaFuncSetAttribute(k_gemm_mma<128, false>,
                         cudaFuncAttributeMaxDynamicSharedMemorySize, SM_TOT);

    // Weight preconversion (tiny)
    __nv_bfloat16 *whh = nullptr, *whl = nullptr, *woh = nullptr, *wol = nullptr;
    cudaGetSymbolAddress((void**)&whh, g_Whid_hi);
    cudaGetSymbolAddress((void**)&whl, g_Whid_lo);
    cudaGetSymbolAddress((void**)&woh, g_Wog_hi);
    cudaGetSymbolAddress((void**)&wol, g_Wog_lo);
    k_wconv<<<(Hz * 256 * N1z + 255) / 256, 256>>>(W_hid, whh, whl, N1z);
    k_wconv<<<(Hz * 256 * 128 + 255) / 256, 256>>>(W_og, woh, wol, 128);

    // Phase 1: exclusive cumsum + LN(csum)
    k_scan1_partial<<<dim3(Bz, NCH), 1024>>>(x);
    k_scan1_offsets<<<Bz, 1024>>>();
    k_scan1_ln<<<dim3(Bz, NCH), 1024>>>(x, g_cs, be_cs);

    // Phase 2: h3 = [x | ln(csum)] @ W_hid + b_hid  (tensor cores, HMMA)
    k_gemm_mma<N1z, true><<<dim3(Sz * Bz / 128, 3, Hz), 256, SM_TOT>>>(x, whh, whl, b_hid);

    // Phase 3: LN(h3), gates, chunk compositions
    k_gates<<<dim3(Bz, NCH), 1024>>>(g_hd, be_hd);

    // Phase 4: recurrent scan c = f*c + i
    k_carry<<<Bz, 1024>>>(init_cx);
    k_replay<<<dim3(Bz, NCH), 1024>>>();

    // Phase 5: og = [x | cell] @ W_og + b_og  (tensor cores, HMMA), LN, sigmoid*cell
    k_gemm_mma<128, false><<<dim3(Sz * Bz / 128, 1, Hz), 256, SM_TOT>>>(x, woh, wol, b_og);
    k_final<<<Bz * Sz, 256>>>(g_ogp, be_ogp, out);
}

// round 9
// speedup vs baseline: 3.9193x; 1.3448x over previous
#include <cuda_runtime.h>
#include <cuda_bf16.h>
#include <cstdint>

#define Bz   4
#define Sz   4096
#define Hz   8
#define Lz   1024      // H * DI
#define N1z  384       // 3 * DO
#define NCH  128       // chunks over S
#define CLEN 32        // S / NCH
#define EPSf 1e-6f

typedef unsigned long long u64;

// ---------------- scratch (static device memory; no allocations) ----------------
static __device__ float  g_csum_ln[(size_t)Bz * Sz * Lz];        // 64 MB
static __device__ float  g_h3[(size_t)Bz * Sz * Hz * N1z];       // 192 MB
static __device__ float2 g_fgi[(size_t)Bz * Sz * Lz];            // 128 MB (f, i)
static __device__ float  g_cell[(size_t)Bz * Sz * Lz];           // 64 MB
static __device__ float  g_og[(size_t)Bz * Sz * Lz];             // 64 MB
static __device__ float  g_chA[Bz * NCH * Lz];
static __device__ float  g_chF[Bz * NCH * Lz];
static __device__ float  g_chAcc[Bz * NCH * Lz];
static __device__ float  g_carry[Bz * NCH * Lz];
// split-bf16 weights, transposed to [h][n][k=256]
static __device__ __nv_bfloat16 g_Whid_hi[Hz * N1z * 256];
static __device__ __nv_bfloat16 g_Whid_lo[Hz * N1z * 256];
static __device__ __nv_bfloat16 g_Wog_hi[Hz * 128 * 256];
static __device__ __nv_bfloat16 g_Wog_lo[Hz * 128 * 256];

// ========================= mma.sync helpers ==========================
__device__ __forceinline__ uint32_t smem_u32(const void* p) {
    uint32_t a;
    asm("{ .reg .u64 t; cvta.to.shared.u64 t, %1; cvt.u32.u64 %0, t; }"
        : "=r"(a) : "l"(p));
    return a;
}
__device__ __forceinline__ void ldsm4(uint32_t* r, uint32_t addr) {
    asm volatile("ldmatrix.sync.aligned.m8n8.x4.shared.b16 {%0,%1,%2,%3}, [%4];"
        : "=r"(r[0]), "=r"(r[1]), "=r"(r[2]), "=r"(r[3]) : "r"(addr));
}
__device__ __forceinline__ void mma16816(float* c, const uint32_t* a, const uint32_t* b) {
    asm volatile(
        "mma.sync.aligned.m16n8k16.row.col.f32.bf16.bf16.f32 "
        "{%0,%1,%2,%3}, {%4,%5,%6,%7}, {%8,%9}, {%0,%1,%2,%3};"
        : "+f"(c[0]), "+f"(c[1]), "+f"(c[2]), "+f"(c[3])
        : "r"(a[0]), "r"(a[1]), "r"(a[2]), "r"(a[3]), "r"(b[0]), "r"(b[1]));
}
__device__ __forceinline__ void cpa16(uint32_t dst, const void* src) {
    asm volatile("cp.async.cg.shared.global [%0], [%1], 16;" :: "r"(dst), "l"(src));
}
#define CP_COMMIT() asm volatile("cp.async.commit_group;")
#define CP_WAIT0()  asm volatile("cp.async.wait_group 0;")

__device__ __forceinline__ uint32_t swz(uint32_t o) { return o ^ ((o >> 3) & 0x70); }
__device__ __forceinline__ uint32_t pack_bf(__nv_bfloat16 a, __nv_bfloat16 b) {
    __nv_bfloat162 t(a, b);
    return *reinterpret_cast<uint32_t*>(&t);
}

// smem: A single-stage (hi/lo), B double-buffered (hi/lo) via cp.async
#define SM_AHI 0
#define SM_ALO 16384
#define SM_BHB(b) (32768 + (b) * 32768)
#define SM_BLB(b) (32768 + (b) * 32768 + 16384)
#define SM_TOT 98304

// =====================================================================
// Fused: Phase-1 chunk sums (blocks x<Bz) + weight transpose/split
// conversion (blocks x>=Bz).  Conversion tiles: 64k x 64n via padded
// smem transpose -> fully coalesced reads AND writes.
// =====================================================================
__global__ void k_partial_wconv(const float* __restrict__ x,
                                const float* __restrict__ W_hid,
                                const float* __restrict__ W_og) {
    __shared__ __nv_bfloat16 smh[64][66];
    __shared__ __nv_bfloat16 sml[64][66];
    const int bx = blockIdx.x, by = blockIdx.y, tid = threadIdx.x;

    if (bx < Bz) {
        const float* p = x + (size_t)(bx * Sz + by * CLEN) * Lz + tid;
        float s0 = 0.f, s1 = 0.f, s2 = 0.f, s3 = 0.f;
        #pragma unroll
        for (int i = 0; i < CLEN; i += 4) {
            s0 += p[(size_t)(i + 0) * Lz];
            s1 += p[(size_t)(i + 1) * Lz];
            s2 += p[(size_t)(i + 2) * Lz];
            s3 += p[(size_t)(i + 3) * Lz];
        }
        g_chA[(bx * NCH + by) * Lz + tid] = (s0 + s1) + (s2 + s3);
        return;
    }

    // weight conversion tile
    const int t = (bx - Bz) * gridDim.y + by;   // 0..255
    const float* W;
    __nv_bfloat16 *hi, *lo;
    int N, h, kt, nt;
    if (t < 192) {
        W = W_hid; hi = g_Whid_hi; lo = g_Whid_lo; N = N1z;
        h = t / 24; const int r = t % 24; kt = r / 6; nt = r % 6;
    } else {
        const int t2 = t - 192;
        W = W_og; hi = g_Wog_hi; lo = g_Wog_lo; N = 128;
        h = t2 / 8; const int r = t2 % 8; kt = r / 2; nt = r % 2;
    }
    #pragma unroll
    for (int i = 0; i < 4; i++) {
        const int idx = tid + i * 1024;
        const int nl = idx & 63, kl = idx >> 6;
        const float v = W[(size_t)(h * 256 + kt * 64 + kl) * N + nt * 64 + nl];
        const __nv_bfloat16 vh = __float2bfloat16(v);
        smh[nl][kl] = vh;
        sml[nl][kl] = __float2bfloat16(v - __bfloat162float(vh));
    }
    __syncthreads();
    {
        const int nl = tid >> 4, k4 = (tid & 15) * 4;
        __nv_bfloat16 h4[4], l4[4];
        #pragma unroll
        for (int j = 0; j < 4; j++) { h4[j] = smh[nl][k4 + j]; l4[j] = sml[nl][k4 + j]; }
        const size_t o = (size_t)(h * N + nt * 64 + nl) * 256 + kt * 64 + k4;
        *(uint2*)(hi + o) = *(uint2*)h4;
        *(uint2*)(lo + o) = *(uint2*)l4;
    }
}

// =====================================================================
// Phase 1b: chunk-offset exclusive scan (MLP-batched loads)
// =====================================================================
__global__ void k_scan1_offsets() {
    const int b = blockIdx.x, l = threadIdx.x;
    float run = 0.f;
    #pragma unroll
    for (int g = 0; g < NCH; g += 16) {
        float v[16];
        #pragma unroll
        for (int j = 0; j < 16; j++)
            v[j] = g_chA[(b * NCH + g + j) * Lz + l];
        #pragma unroll
        for (int j = 0; j < 16; j++) {
            g_chA[(b * NCH + g + j) * Lz + l] = run;
            run += v[j];
        }
    }
}

__global__ void k_scan1_ln(const float* __restrict__ x,
                           const float* __restrict__ gam,
                           const float* __restrict__ bet) {
    __shared__ float sred[64];
    __shared__ float s_stats[2];
    const int b = blockIdx.x, ch = blockIdx.y, l = threadIdx.x;
    const int wid = l >> 5, lane = l & 31;
    float c = g_chA[(b * NCH + ch) * Lz + l];
    const float gv = gam[l], bv = bet[l];
    const float* p = x + (size_t)(b * Sz + ch * CLEN) * Lz + l;
    float* o = g_csum_ln + (size_t)(b * Sz + ch * CLEN) * Lz + l;
    for (int i = 0; i < CLEN; i++) {
        const float v = c;
        float r1 = v, r2 = v * v;
        #pragma unroll
        for (int off = 16; off > 0; off >>= 1) {
            r1 += __shfl_down_sync(0xffffffffu, r1, off);
            r2 += __shfl_down_sync(0xffffffffu, r2, off);
        }
        if (lane == 0) { sred[wid] = r1; sred[32 + wid] = r2; }
        __syncthreads();
        if (wid == 0) {
            float t1 = sred[lane], t2 = sred[32 + lane];
            #pragma unroll
            for (int off = 16; off > 0; off >>= 1) {
                t1 += __shfl_down_sync(0xffffffffu, t1, off);
                t2 += __shfl_down_sync(0xffffffffu, t2, off);
            }
            if (lane == 0) {
                const float mu = t1 * (1.f / 1024.f);
                s_stats[0] = mu;
                s_stats[1] = rsqrtf(t2 * (1.f / 1024.f) - mu * mu + EPSf);
            }
        }
        __syncthreads();
        o[(size_t)i * Lz] = (v - s_stats[0]) * s_stats[1] * gv + bv;
        c += p[(size_t)i * Lz];
    }
}

// =====================================================================
// Tensor-core batched per-head GEMM, 3-term bf16 split, mma.sync HMMA.
// B double-buffered via cp.async (overlaps compute); A converted in the
// staging phase (single buffer).  CTA tile 128x128, 8 warps (4m x 2n).
// =====================================================================
template <int NLD, bool PHASE1>
__global__ __launch_bounds__(256, 2) void k_gemm_mma(const float* __restrict__ A0,
                                                     const __nv_bfloat16* __restrict__ Bhi,
                                                     const __nv_bfloat16* __restrict__ Blo,
                                                     const float* __restrict__ bias) {
    const float* __restrict__ A1 = PHASE1 ? g_csum_ln : g_cell;
    float* __restrict__ C = PHASE1 ? g_h3 : g_og;

    extern __shared__ char sm[];
    const uint32_t sb = smem_u32(sm);
    const int tid = threadIdx.x;
    const int lane = tid & 31, wid = tid >> 5;
    const int m0 = blockIdx.x * 128, n0 = blockIdx.y * 128, h = blockIdx.z;
    const int wm = (wid & 3) * 32;
    const int wn = (wid >> 2) * 64;

    float acc[2][8][4];
    #pragma unroll
    for (int mt = 0; mt < 2; mt++)
        #pragma unroll
        for (int nt = 0; nt < 8; nt++)
            #pragma unroll
            for (int q = 0; q < 4; q++) acc[mt][nt][q] = 0.f;

    const int aq = lane >> 3;
    const int arow_l = (aq & 1) * 8 + (lane & 7);
    const int akb    = (aq >> 1) * 16;
    const int brow_l = (aq >> 1) * 8 + (lane & 7);
    const int bkb    = (aq & 1) * 16;

    // B async staging lambda-equivalent (macro-free inline)
    const int bq = tid & 7;
    const int bn_base = tid >> 3;

    // ---- prologue: async B(0), stage A(0) ----
    {
        #pragma unroll
        for (int j = 0; j < 4; j++) {
            const int n = bn_base + j * 32;
            const size_t goff = ((size_t)(h * NLD + n0 + n) * 256 + 0 * 64);
            const uint32_t so = swz((uint32_t)(n * 128 + bq * 16));
            cpa16(sb + SM_BHB(0) + so, Bhi + goff + bq * 8);
            cpa16(sb + SM_BLB(0) + so, Blo + goff + bq * 8);
        }
        CP_COMMIT();
    }
    {
        const int col = (tid & 15) * 4;
        #pragma unroll
        for (int j = 0; j < 8; j++) {
            const int row = (tid >> 4) + j * 16;
            const float4 v = *(const float4*)(A0 +
                ((size_t)(m0 + row) * Hz + h) * 128 + col);
            const __nv_bfloat16 h0 = __float2bfloat16(v.x);
            const __nv_bfloat16 h1 = __float2bfloat16(v.y);
            const __nv_bfloat16 h2 = __float2bfloat16(v.z);
            const __nv_bfloat16 h3 = __float2bfloat16(v.w);
            const __nv_bfloat16 l0 = __float2bfloat16(v.x - __bfloat162float(h0));
            const __nv_bfloat16 l1 = __float2bfloat16(v.y - __bfloat162float(h1));
            const __nv_bfloat16 l2 = __float2bfloat16(v.z - __bfloat162float(h2));
            const __nv_bfloat16 l3 = __float2bfloat16(v.w - __bfloat162float(h3));
            const uint32_t so = swz((uint32_t)(row * 128 + col * 2));
            *(uint2*)(sm + SM_AHI + so) = make_uint2(pack_bf(h0, h1), pack_bf(h2, h3));
            *(uint2*)(sm + SM_ALO + so) = make_uint2(pack_bf(l0, l1), pack_bf(l2, l3));
        }
    }
    CP_WAIT0();
    __syncthreads();

    #pragma unroll 1
    for (int c = 0; c < 4; c++) {
        // issue async B(c+1) into the other buffer (overlaps compute)
        if (c < 3) {
            #pragma unroll
            for (int j = 0; j < 4; j++) {
                const int n = bn_base + j * 32;
                const size_t goff = ((size_t)(h * NLD + n0 + n) * 256 + (c + 1) * 64);
                const uint32_t so = swz((uint32_t)(n * 128 + bq * 16));
                cpa16(sb + SM_BHB((c + 1) & 1) + so, Bhi + goff + bq * 8);
                cpa16(sb + SM_BLB((c + 1) & 1) + so, Blo + goff + bq * 8);
            }
            CP_COMMIT();
        }

        // ---- compute chunk c ----
        const uint32_t bhb = SM_BHB(c & 1), blb = SM_BLB(c & 1);
        #pragma unroll
        for (int k16 = 0; k16 < 4; k16++) {
            uint32_t ahi[2][4], alo[2][4];
            #pragma unroll
            for (int mt = 0; mt < 2; mt++) {
                const uint32_t off =
                    swz((uint32_t)((wm + mt * 16 + arow_l) * 128 + k16 * 32 + akb));
                ldsm4(ahi[mt], sb + SM_AHI + off);
                ldsm4(alo[mt], sb + SM_ALO + off);
            }
            #pragma unroll
            for (int np = 0; np < 4; np++) {
                uint32_t bhi[4], blo[4];
                const uint32_t off =
                    swz((uint32_t)((wn + np * 16 + brow_l) * 128 + k16 * 32 + bkb));
                ldsm4(bhi, sb + bhb + off);
                ldsm4(blo, sb + blb + off);
                #pragma unroll
                for (int mt = 0; mt < 2; mt++) {
                    mma16816(acc[mt][np * 2],     ahi[mt], bhi);
                    mma16816(acc[mt][np * 2],     alo[mt], bhi);
                    mma16816(acc[mt][np * 2],     ahi[mt], blo);
                    mma16816(acc[mt][np * 2 + 1], ahi[mt], bhi + 2);
                    mma16816(acc[mt][np * 2 + 1], alo[mt], bhi + 2);
                    mma16816(acc[mt][np * 2 + 1], ahi[mt], blo + 2);
                }
            }
        }

        // ---- stage A(c+1) (after all warps done reading Asm) ----
        if (c < 3) {
            __syncthreads();
            const float* Asrc = (c + 1 < 2) ? A0 : A1;
            const int kb = ((c + 1) & 1) * 64;
            const int col = (tid & 15) * 4;
            #pragma unroll
            for (int j = 0; j < 8; j++) {
                const int row = (tid >> 4) + j * 16;
                const float4 v = *(const float4*)(Asrc +
                    ((size_t)(m0 + row) * Hz + h) * 128 + kb + col);
                const __nv_bfloat16 h0 = __float2bfloat16(v.x);
                const __nv_bfloat16 h1 = __float2bfloat16(v.y);
                const __nv_bfloat16 h2 = __float2bfloat16(v.z);
                const __nv_bfloat16 h3 = __float2bfloat16(v.w);
                const __nv_bfloat16 l0 = __float2bfloat16(v.x - __bfloat162float(h0));
                const __nv_bfloat16 l1 = __float2bfloat16(v.y - __bfloat162float(h1));
                const __nv_bfloat16 l2 = __float2bfloat16(v.z - __bfloat162float(h2));
                const __nv_bfloat16 l3 = __float2bfloat16(v.w - __bfloat162float(h3));
                const uint32_t so = swz((uint32_t)(row * 128 + col * 2));
                *(uint2*)(sm + SM_AHI + so) = make_uint2(pack_bf(h0, h1), pack_bf(h2, h3));
                *(uint2*)(sm + SM_ALO + so) = make_uint2(pack_bf(l0, l1), pack_bf(l2, l3));
            }
            CP_WAIT0();
            __syncthreads();
        }
    }

    // ---- epilogue ----
    #pragma unroll
    for (int mt = 0; mt < 2; mt++) {
        const int r0 = m0 + wm + mt * 16 + (lane >> 2);
        #pragma unroll
        for (int nt = 0; nt < 8; nt++) {
            const int col = n0 + wn + nt * 8 + (lane & 3) * 2;
            const float2 bv = *(const float2*)(bias + h * NLD + col);
            float2 o0, o1;
            o0.x = acc[mt][nt][0] + bv.x;  o0.y = acc[mt][nt][1] + bv.y;
            o1.x = acc[mt][nt][2] + bv.x;  o1.y = acc[mt][nt][3] + bv.y;
            *(float2*)(C + ((size_t)r0 * Hz + h) * NLD + col)       = o0;
            *(float2*)(C + ((size_t)(r0 + 8) * Hz + h) * NLD + col) = o1;
        }
    }
}

// =====================================================================
// Phase 3: LN over (H,3,DO) per (b,s), gates, per-chunk scan composition
// =====================================================================
__global__ void k_gates(const float* __restrict__ gam, const float* __restrict__ bet) {
    __shared__ float row[3072];
    __shared__ float sred[64];
    __shared__ float s_stats[2];
    const int b = blockIdx.x, ch = blockIdx.y, l = threadIdx.x;
    const int wid = l >> 5, lane = l & 31;
    const int h = l >> 7, dd = l & 127;
    const int pb = (h * 3) * 128 + dd;
    const float gi = gam[pb], gf = gam[pb + 128], gh = gam[pb + 256];
    const float bi = bet[pb], bf = bet[pb + 128], bh = bet[pb + 256];
    float F = 1.f, Acc = 0.f;
    for (int i = 0; i < CLEN; i++) {
        const size_t rb = (size_t)(b * Sz + ch * CLEN + i) * (Hz * N1z);
        const float v0 = g_h3[rb + l];
        const float v1 = g_h3[rb + 1024 + l];
        const float v2 = g_h3[rb + 2048 + l];
        row[l] = v0; row[1024 + l] = v1; row[2048 + l] = v2;
        float r1 = v0 + v1 + v2;
        float r2 = v0 * v0 + v1 * v1 + v2 * v2;
        #pragma unroll
        for (int off = 16; off > 0; off >>= 1) {
            r1 += __shfl_down_sync(0xffffffffu, r1, off);
            r2 += __shfl_down_sync(0xffffffffu, r2, off);
        }
        if (lane == 0) { sred[wid] = r1; sred[32 + wid] = r2; }
        __syncthreads();
        if (wid == 0) {
            float t1 = sred[lane], t2 = sred[32 + lane];
            #pragma unroll
            for (int off = 16; off > 0; off >>= 1) {
                t1 += __shfl_down_sync(0xffffffffu, t1, off);
                t2 += __shfl_down_sync(0xffffffffu, t2, off);
            }
            if (lane == 0) {
                const float mu = t1 * (1.f / 3072.f);
                s_stats[0] = mu;
                s_stats[1] = rsqrtf(t2 * (1.f / 3072.f) - mu * mu + EPSf);
            }
        }
        __syncthreads();
        const float mu = s_stats[0], rs = s_stats[1];
        const int base = h * N1z + dd;
        const float xig = (row[base]       - mu) * rs * gi + bi;
        const float xfg = (row[base + 128] - mu) * rs * gf + bf;
        const float xhd = (row[base + 256] - mu) * rs * gh + bh;
        const float f  = 1.f / (1.f + __expf(-xfg));
        const float ii = (1.f / (1.f + __expf(-xig))) * fmaxf(xhd, 0.f);
        g_fgi[(size_t)(b * Sz + ch * CLEN + i) * Lz + l] = make_float2(f, ii);
        Acc = f * Acc + ii;
        F *= f;
        __syncthreads();
    }
    const int ci = (b * NCH + ch) * Lz + l;
    g_chF[ci] = F;
    g_chAcc[ci] = Acc;
}

// =====================================================================
// Phase 4a: chunk-carry scan (MLP-batched loads)
// =====================================================================
__global__ void k_carry(const float* __restrict__ init_cx) {
    const int b = blockIdx.x, l = threadIdx.x;
    float c = init_cx[l];
    #pragma unroll
    for (int g = 0; g < NCH; g += 16) {
        float vf[16], va[16];
        #pragma unroll
        for (int j = 0; j < 16; j++) {
            const int idx = (b * NCH + g + j) * Lz + l;
            vf[j] = g_chF[idx];
            va[j] = g_chAcc[idx];
        }
        #pragma unroll
        for (int j = 0; j < 16; j++) {
            g_carry[(b * NCH + g + j) * Lz + l] = c;
            c = vf[j] * c + va[j];
        }
    }
}

__global__ void k_replay() {
    const int b = blockIdx.x, ch = blockIdx.y, l = threadIdx.x;
    float c = g_carry[(b * NCH + ch) * Lz + l];
    const size_t base = (size_t)(b * Sz + ch * CLEN) * Lz + l;
    #pragma unroll 8
    for (int i = 0; i < CLEN; i++) {
        const float2 fi = g_fgi[base + (size_t)i * Lz];
        c = fi.x * c + fi.y;
        g_cell[base + (size_t)i * Lz] = c;
    }
}

// =====================================================================
// Phase 5: LN over (H,DO) per (b,s), sigmoid(og) * cell -> out
// =====================================================================
__global__ void k_final(const float* __restrict__ gam, const float* __restrict__ bet,
                        float* __restrict__ out) {
    __shared__ float sred[16];
    __shared__ float s_stats[2];
    const int bs = blockIdx.x, t = threadIdx.x;
    const int wid = t >> 5, lane = t & 31;
    const size_t base = (size_t)bs * Lz + t * 4;
    const float4 v = *(const float4*)(g_og + base);
    float r1 = v.x + v.y + v.z + v.w;
    float r2 = v.x * v.x + v.y * v.y + v.z * v.z + v.w * v.w;
    #pragma unroll
    for (int off = 16; off > 0; off >>= 1) {
        r1 += __shfl_down_sync(0xffffffffu, r1, off);
        r2 += __shfl_down_sync(0xffffffffu, r2, off);
    }
    if (lane == 0) { sred[wid] = r1; sred[8 + wid] = r2; }
    __syncthreads();
    if (wid == 0) {
        float t1 = lane < 8 ? sred[lane] : 0.f;
        float t2 = lane < 8 ? sred[8 + lane] : 0.f;
        #pragma unroll
        for (int off = 4; off > 0; off >>= 1) {
            t1 += __shfl_down_sync(0xffffffffu, t1, off);
            t2 += __shfl_down_sync(0xffffffffu, t2, off);
        }
        if (lane == 0) {
            const float mu = t1 * (1.f / 1024.f);
            s_stats[0] = mu;
            s_stats[1] = rsqrtf(t2 * (1.f / 1024.f) - mu * mu + EPSf);
        }
    }
    __syncthreads();
    const float mu = s_stats[0], rs = s_stats[1];
    const float4 cc = *(const float4*)(g_cell + base);
    const float4 gg = *(const float4*)(gam + t * 4);
    const float4 bb = *(const float4*)(bet + t * 4);
    float4 o;
    o.x = cc.x / (1.f + __expf(-((v.x - mu) * rs * gg.x + bb.x)));
    o.y = cc.y / (1.f + __expf(-((v.y - mu) * rs * gg.y + bb.y)));
    o.z = cc.z / (1.f + __expf(-((v.z - mu) * rs * gg.z + bb.z)));
    o.w = cc.w / (1.f + __expf(-((v.w - mu) * rs * gg.w + bb.w)));
    *(float4*)(out + base) = o;
}

// =====================================================================
extern "C" void kernel_launch(void* const* d_in, const int* in_sizes, int n_in,
                              void* d_out, int out_size) {
    (void)in_sizes; (void)n_in; (void)out_size;
    const float* x       = (const float*)d_in[0];
    const float* W_hid   = (const float*)d_in[1];
    const float* b_hid   = (const float*)d_in[2];
    const float* g_cs    = (const float*)d_in[3];
    const float* be_cs   = (const float*)d_in[4];
    const float* g_hd    = (const float*)d_in[5];
    const float* be_hd   = (const float*)d_in[6];
    const float* W_og    = (const float*)d_in[7];
    const float* b_og    = (const float*)d_in[8];
    const float* g_ogp   = (const float*)d_in[9];
    const float* be_ogp  = (const float*)d_in[10];
    const float* init_cx = (const float*)d_in[11];
    float* out = (float*)d_out;

    cudaFuncSetAttribute(k_gemm_mma<N1z, true>,
                         cudaFuncAttributeMaxDynamicSharedMemorySize, SM_TOT);
    cudaFuncSetAttribute(k_gemm_mma<128, false>,
                         cudaFuncAttributeMaxDynamicSharedMemorySize, SM_TOT);

    __nv_bfloat16 *whh = nullptr, *whl = nullptr, *woh = nullptr, *wol = nullptr;
    cudaGetSymbolAddress((void**)&whh, g_Whid_hi);
    cudaGetSymbolAddress((void**)&whl, g_Whid_lo);
    cudaGetSymbolAddress((void**)&woh, g_Wog_hi);
    cudaGetSymbolAddress((void**)&wol, g_Wog_lo);

    // 1: Phase-1 partial sums + weight conversion (fused)
    k_partial_wconv<<<dim3(Bz + 2, NCH), 1024>>>(x, W_hid, W_og);
    // 2: chunk offsets
    k_scan1_offsets<<<Bz, 1024>>>();
    // 3: cumsum LN
    k_scan1_ln<<<dim3(Bz, NCH), 1024>>>(x, g_cs, be_cs);
    // 4: GEMM1 (captured by ncu)
    k_gemm_mma<N1z, true><<<dim3(Sz * Bz / 128, 3, Hz), 256, SM_TOT>>>(x, whh, whl, b_hid);
    // 5: gates
    k_gates<<<dim3(Bz, NCH), 1024>>>(g_hd, be_hd);
    // 6: carry
    k_carry<<<Bz, 1024>>>(init_cx);
    // 7: replay
    k_replay<<<dim3(Bz, NCH), 1024>>>();
    // 8: GEMM2
    k_gemm_mma<128, false><<<dim3(Sz * Bz / 128, 1, Hz), 256, SM_TOT>>>(x, woh, wol, b_og);
    // 9: final
    k_final<<<Bz * Sz, 256>>>(g_ogp, be_ogp, out);
}